// round 1
// baseline (speedup 1.0000x reference)
#include <cuda_runtime.h>
#include <mma.h>
#include <math.h>

using namespace nvcuda;

#define BATCH 8
#define SEQ   2048
#define DIM   512
#define NH    8
#define HD    64
#define BM    (BATCH*SEQ)   // 16384

// ---------------- scratch (static device memory; no allocations allowed) ----
__device__ __align__(16) float g_theta[256];
__device__ __align__(16) float g_cs[SEQ][256][2];              // cos, sin per (pos, pair)
__device__ __align__(16) float g_YR[(size_t)BM * 1536];        // rot(x@Wq^T) | rot(x@Wk^T) | rot(x@Wv^T)
__device__ __align__(16) float g_QKV[(size_t)3 * BATCH * NH * SEQ * HD]; // [qkv][b][h][m][hd]
__device__ __align__(16) float g_ctx[(size_t)BM * DIM];        // attention output [b][m][d]

__device__ __forceinline__ float to_tf32(float x) { return wmma::__float_to_tf32(x); }

// ---------------- setup: theta (double pow, matches fp32 correctly-rounded) --
__global__ void setup_theta_kernel() {
    int i = threadIdx.x;  // 0..255
    double e = -2.0 * ((double)i - 1.0) / 512.0;
    g_theta[i] = (float)pow(10000.0, e);
}

// cos/sin table: angle computed exactly like the reference (fp32 pos * fp32 theta)
__global__ void setup_cs_kernel() {
    int pos = blockIdx.x;
    int i = threadIdx.x;
    float ang = (float)pos * g_theta[i];
    float s, c;
    sincosf(ang, &s, &c);
    g_cs[pos][i][0] = c;
    g_cs[pos][i][1] = s;
}

// ---------------- generic 64x64 tiled TF32 GEMM, 3 modes ---------------------
// MODE 0: YR = rope(x @ {w_q,w_k,w_v}^T),   N=1536, writes g_YR
// MODE 1: QKV = YR @ in_proj_w^T + b,       N=1536, writes g_QKV [qkv][b][h][m][hd], Q scaled by 0.125
// MODE 2: out = g_ctx @ out_w^T + out_b,    N=512,  writes Cout (d_out)
template<int MODE>
__global__ __launch_bounds__(128) void gemm64(
    const float* __restrict__ A,
    const float* __restrict__ B0,
    const float* __restrict__ B1,
    const float* __restrict__ B2,
    const float* __restrict__ bias,
    float* __restrict__ Cout)
{
    __shared__ __align__(32) float As[64][40];
    __shared__ __align__(32) float Bs[64][40];
    __shared__ __align__(32) float Csm[64][72];

    const int m0  = blockIdx.y * 64;
    const int n0g = blockIdx.x * 64;
    const int seg = n0g >> 9;        // which 512-col segment (q/k/v)
    const int n0  = n0g & 511;

    const float* Bp;
    const float* Ap;
    int lda;
    if (MODE == 0) {
        const float* Bsel = (seg == 0) ? B0 : ((seg == 1) ? B1 : B2);
        Bp = Bsel + (size_t)n0 * DIM;
        Ap = A + (size_t)m0 * DIM;  lda = DIM;
    } else if (MODE == 1) {
        Bp = B0 + (size_t)n0g * DIM;                 // in_proj_w rows n0g..n0g+63
        Ap = g_YR + (size_t)m0 * 1536 + seg * DIM;   // matching rotated segment
        lda = 1536;
    } else {
        Bp = B0 + (size_t)n0g * DIM;
        Ap = g_ctx + (size_t)m0 * DIM;  lda = DIM;
    }

    const int t = threadIdx.x;
    const int warp = t >> 5;
    const int wr = warp >> 1, wc = warp & 1;

    wmma::fragment<wmma::accumulator, 16, 16, 8, float> acc[2][2];
    #pragma unroll
    for (int i = 0; i < 2; i++)
        #pragma unroll
        for (int j = 0; j < 2; j++) wmma::fill_fragment(acc[i][j], 0.f);

    for (int k0 = 0; k0 < DIM; k0 += 32) {
        #pragma unroll
        for (int it = 0; it < 4; it++) {
            int idx = t + it * 128;        // 0..511 float4 slots
            int row = idx >> 3;
            int kc  = (idx & 7) << 2;
            float4 va = *reinterpret_cast<const float4*>(Ap + (size_t)row * lda + k0 + kc);
            As[row][kc+0] = to_tf32(va.x); As[row][kc+1] = to_tf32(va.y);
            As[row][kc+2] = to_tf32(va.z); As[row][kc+3] = to_tf32(va.w);
            float4 vb = *reinterpret_cast<const float4*>(Bp + (size_t)row * DIM + k0 + kc);
            Bs[row][kc+0] = to_tf32(vb.x); Bs[row][kc+1] = to_tf32(vb.y);
            Bs[row][kc+2] = to_tf32(vb.z); Bs[row][kc+3] = to_tf32(vb.w);
        }
        __syncthreads();
        #pragma unroll
        for (int kk = 0; kk < 32; kk += 8) {
            wmma::fragment<wmma::matrix_a, 16, 16, 8, wmma::precision::tf32, wmma::row_major> a0, a1;
            wmma::fragment<wmma::matrix_b, 16, 16, 8, wmma::precision::tf32, wmma::col_major> b0, b1;
            wmma::load_matrix_sync(a0, &As[wr*32     ][kk], 40);
            wmma::load_matrix_sync(a1, &As[wr*32 + 16][kk], 40);
            wmma::load_matrix_sync(b0, &Bs[wc*32     ][kk], 40);
            wmma::load_matrix_sync(b1, &Bs[wc*32 + 16][kk], 40);
            wmma::mma_sync(acc[0][0], a0, b0, acc[0][0]);
            wmma::mma_sync(acc[0][1], a0, b1, acc[0][1]);
            wmma::mma_sync(acc[1][0], a1, b0, acc[1][0]);
            wmma::mma_sync(acc[1][1], a1, b1, acc[1][1]);
        }
        __syncthreads();
    }

    wmma::store_matrix_sync(&Csm[wr*32     ][wc*32     ], acc[0][0], 72, wmma::mem_row_major);
    wmma::store_matrix_sync(&Csm[wr*32     ][wc*32 + 16], acc[0][1], 72, wmma::mem_row_major);
    wmma::store_matrix_sync(&Csm[wr*32 + 16][wc*32     ], acc[1][0], 72, wmma::mem_row_major);
    wmma::store_matrix_sync(&Csm[wr*32 + 16][wc*32 + 16], acc[1][1], 72, wmma::mem_row_major);
    __syncthreads();

    if (MODE == 0) {
        // RoPE epilogue: pairs (even, odd) within the 512-wide segment
        for (int idx = t; idx < 64 * 32; idx += 128) {
            int row = idx >> 5;
            int c   = (idx & 31) << 1;
            int gm  = m0 + row;
            int pos = gm & (SEQ - 1);
            int tp  = (n0 + c) >> 1;
            float e = Csm[row][c], o = Csm[row][c+1];
            float cc = g_cs[pos][tp][0], ss = g_cs[pos][tp][1];
            size_t base = (size_t)gm * 1536 + n0g + c;
            g_YR[base]     =  e * cc + o * ss;
            g_YR[base + 1] = -e * ss + o * cc;
        }
    } else if (MODE == 1) {
        for (int idx = t; idx < 64 * 64; idx += 128) {
            int row = idx >> 6;
            int c   = idx & 63;
            int gm  = m0 + row;
            float v = Csm[row][c] + bias[n0g + c];
            int batch = gm >> 11, pos = gm & (SEQ - 1);
            int jj   = n0 + c;
            int head = jj >> 6, dd = jj & 63;
            if (seg == 0) v *= 0.125f;  // fold attention scale 1/sqrt(64) into Q
            g_QKV[((((size_t)seg * BATCH + batch) * NH + head) * SEQ + pos) * HD + dd] = v;
        }
    } else {
        for (int idx = t; idx < 64 * 64; idx += 128) {
            int row = idx >> 6;
            int c   = idx & 63;
            int gm  = m0 + row;
            Cout[(size_t)gm * DIM + n0g + c] = Csm[row][c] + bias[n0g + c];
        }
    }
}

// ---------------- flash attention: causal, 64-row q tiles, tf32 MMA ----------
#define TLD 72
#define FLASH_SMEM (5 * 64 * TLD * 4)

__global__ __launch_bounds__(128) void flash_kernel()
{
    extern __shared__ float sm[];
    float* Qs = sm;
    float* Ks = sm + 1 * 64 * TLD;
    float* Vs = sm + 2 * 64 * TLD;
    float* Ss = sm + 3 * 64 * TLD;
    float* Os = sm + 4 * 64 * TLD;

    const int bh = blockIdx.x;            // 0..63
    const int qt = 31 - blockIdx.y;       // heavy tiles first
    const int batch = bh >> 3, head = bh & 7;

    const float* Qg = g_QKV + ((size_t)(0 * BATCH + batch) * NH + head) * SEQ * HD;
    const float* Kg = g_QKV + ((size_t)(1 * BATCH + batch) * NH + head) * SEQ * HD;
    const float* Vg = g_QKV + ((size_t)(2 * BATCH + batch) * NH + head) * SEQ * HD;

    const int t = threadIdx.x;
    const int warp = t >> 5;
    const int wr = warp >> 1, wc = warp & 1;

    for (int idx = t; idx < 64 * 64; idx += 128) {
        int r = idx >> 6, c = idx & 63;
        Qs[r * TLD + c] = to_tf32(Qg[(size_t)(qt * 64 + r) * HD + c]);
        Os[r * TLD + c] = 0.f;
    }
    float m_i = -INFINITY, l_i = 0.f;
    __syncthreads();

    for (int kt = 0; kt <= qt; kt++) {
        // load K, V tiles
        for (int idx = t; idx < 64 * 64; idx += 128) {
            int r = idx >> 6, c = idx & 63;
            Ks[r * TLD + c] = to_tf32(Kg[(size_t)(kt * 64 + r) * HD + c]);
            Vs[r * TLD + c] = to_tf32(Vg[(size_t)(kt * 64 + r) * HD + c]);
        }
        __syncthreads();

        // S = Q @ K^T  (k over hd=64)
        {
            wmma::fragment<wmma::accumulator, 16, 16, 8, float> sacc[2][2];
            #pragma unroll
            for (int i = 0; i < 2; i++)
                #pragma unroll
                for (int j = 0; j < 2; j++) wmma::fill_fragment(sacc[i][j], 0.f);
            #pragma unroll
            for (int kk = 0; kk < 64; kk += 8) {
                wmma::fragment<wmma::matrix_a, 16, 16, 8, wmma::precision::tf32, wmma::row_major> a0, a1;
                wmma::fragment<wmma::matrix_b, 16, 16, 8, wmma::precision::tf32, wmma::col_major> b0, b1;
                wmma::load_matrix_sync(a0, &Qs[(wr*32     ) * TLD + kk], TLD);
                wmma::load_matrix_sync(a1, &Qs[(wr*32 + 16) * TLD + kk], TLD);
                wmma::load_matrix_sync(b0, &Ks[(wc*32     ) * TLD + kk], TLD);
                wmma::load_matrix_sync(b1, &Ks[(wc*32 + 16) * TLD + kk], TLD);
                wmma::mma_sync(sacc[0][0], a0, b0, sacc[0][0]);
                wmma::mma_sync(sacc[0][1], a0, b1, sacc[0][1]);
                wmma::mma_sync(sacc[1][0], a1, b0, sacc[1][0]);
                wmma::mma_sync(sacc[1][1], a1, b1, sacc[1][1]);
            }
            wmma::store_matrix_sync(&Ss[(wr*32     ) * TLD + wc*32     ], sacc[0][0], TLD, wmma::mem_row_major);
            wmma::store_matrix_sync(&Ss[(wr*32     ) * TLD + wc*32 + 16], sacc[0][1], TLD, wmma::mem_row_major);
            wmma::store_matrix_sync(&Ss[(wr*32 + 16) * TLD + wc*32     ], sacc[1][0], TLD, wmma::mem_row_major);
            wmma::store_matrix_sync(&Ss[(wr*32 + 16) * TLD + wc*32 + 16], sacc[1][1], TLD, wmma::mem_row_major);
        }
        __syncthreads();

        // online softmax (one thread per query row)
        if (t < 64) {
            int r = t;
            int climit = (kt == qt) ? (r + 1) : 64;   // causal mask on diagonal tile
            float mx = m_i;
            for (int c = 0; c < climit; c++) mx = fmaxf(mx, Ss[r * TLD + c]);
            float alpha = __expf(m_i - mx);
            float sum = 0.f;
            for (int c = 0; c < 64; c++) {
                float p = (c < climit) ? __expf(Ss[r * TLD + c] - mx) : 0.f;
                Ss[r * TLD + c] = to_tf32(p);
                sum += p;
            }
            l_i = l_i * alpha + sum;
            m_i = mx;
            for (int c = 0; c < 64; c++) Os[r * TLD + c] *= alpha;
        }
        __syncthreads();

        // O += P @ V  (k over 64 keys)
        {
            wmma::fragment<wmma::accumulator, 16, 16, 8, float> oacc[2][2];
            wmma::load_matrix_sync(oacc[0][0], &Os[(wr*32     ) * TLD + wc*32     ], TLD, wmma::mem_row_major);
            wmma::load_matrix_sync(oacc[0][1], &Os[(wr*32     ) * TLD + wc*32 + 16], TLD, wmma::mem_row_major);
            wmma::load_matrix_sync(oacc[1][0], &Os[(wr*32 + 16) * TLD + wc*32     ], TLD, wmma::mem_row_major);
            wmma::load_matrix_sync(oacc[1][1], &Os[(wr*32 + 16) * TLD + wc*32 + 16], TLD, wmma::mem_row_major);
            #pragma unroll
            for (int kk = 0; kk < 64; kk += 8) {
                wmma::fragment<wmma::matrix_a, 16, 16, 8, wmma::precision::tf32, wmma::row_major> a0, a1;
                wmma::fragment<wmma::matrix_b, 16, 16, 8, wmma::precision::tf32, wmma::row_major> b0, b1;
                wmma::load_matrix_sync(a0, &Ss[(wr*32     ) * TLD + kk], TLD);
                wmma::load_matrix_sync(a1, &Ss[(wr*32 + 16) * TLD + kk], TLD);
                wmma::load_matrix_sync(b0, &Vs[kk * TLD + wc*32     ], TLD);
                wmma::load_matrix_sync(b1, &Vs[kk * TLD + wc*32 + 16], TLD);
                wmma::mma_sync(oacc[0][0], a0, b0, oacc[0][0]);
                wmma::mma_sync(oacc[0][1], a0, b1, oacc[0][1]);
                wmma::mma_sync(oacc[1][0], a1, b0, oacc[1][0]);
                wmma::mma_sync(oacc[1][1], a1, b1, oacc[1][1]);
            }
            wmma::store_matrix_sync(&Os[(wr*32     ) * TLD + wc*32     ], oacc[0][0], TLD, wmma::mem_row_major);
            wmma::store_matrix_sync(&Os[(wr*32     ) * TLD + wc*32 + 16], oacc[0][1], TLD, wmma::mem_row_major);
            wmma::store_matrix_sync(&Os[(wr*32 + 16) * TLD + wc*32     ], oacc[1][0], TLD, wmma::mem_row_major);
            wmma::store_matrix_sync(&Os[(wr*32 + 16) * TLD + wc*32 + 16], oacc[1][1], TLD, wmma::mem_row_major);
        }
        __syncthreads();
    }

    if (t < 64) {
        int r = t;
        float inv = 1.f / l_i;
        size_t orow = ((size_t)batch * SEQ + qt * 64 + r) * DIM + head * HD;
        for (int c = 0; c < 64; c++) g_ctx[orow + c] = Os[r * TLD + c] * inv;
    }
}

// ---------------- launch ----------------------------------------------------
extern "C" void kernel_launch(void* const* d_in, const int* in_sizes, int n_in,
                              void* d_out, int out_size)
{
    const float* x         = (const float*)d_in[0];
    const float* w_q       = (const float*)d_in[1];
    const float* w_k       = (const float*)d_in[2];
    const float* w_v       = (const float*)d_in[3];
    const float* in_proj_w = (const float*)d_in[4];
    const float* in_proj_b = (const float*)d_in[5];
    const float* out_w     = (const float*)d_in[6];
    const float* out_b     = (const float*)d_in[7];
    float* out = (float*)d_out;

    setup_theta_kernel<<<1, 256>>>();
    setup_cs_kernel<<<SEQ, 256>>>();

    // rot(x @ W^T) for q,k,v  (N = 1536)
    gemm64<0><<<dim3(24, 256), 128>>>(x, w_q, w_k, w_v, nullptr, nullptr);

    // in_proj + bias -> QKV [qkv][b][h][m][hd], Q pre-scaled
    gemm64<1><<<dim3(24, 256), 128>>>(nullptr, in_proj_w, nullptr, nullptr, in_proj_b, nullptr);

    // causal flash attention -> g_ctx [b][m][d]
    cudaFuncSetAttribute(flash_kernel, cudaFuncAttributeMaxDynamicSharedMemorySize, FLASH_SMEM);
    flash_kernel<<<dim3(64, 32), 128, FLASH_SMEM>>>();

    // out projection + bias -> d_out
    gemm64<2><<<dim3(8, 256), 128>>>(nullptr, out_w, nullptr, nullptr, out_b, out);
}

// round 2
// speedup vs baseline: 1.6707x; 1.6707x over previous
#include <cuda_runtime.h>
#include <mma.h>
#include <math.h>
#include <stdint.h>

using namespace nvcuda;

#define BATCH 8
#define SEQ   2048
#define DIM   512
#define NH    8
#define HD    64
#define BM    (BATCH*SEQ)   // 16384

// ---------------- scratch (static device memory; no allocations allowed) ----
__device__ __align__(16) float g_theta[256];
__device__ __align__(16) float g_cs[SEQ][256][2];              // cos, sin per (pos, pair)
__device__ __align__(16) float g_YR[(size_t)BM * 1536];        // rot(x@Wq^T) | rot(x@Wk^T) | rot(x@Wv^T)
__device__ __align__(16) float g_QKV[(size_t)3 * BATCH * NH * SEQ * HD]; // [qkv][b][h][m][hd]
__device__ __align__(16) float g_ctx[(size_t)BM * DIM];        // attention output [b][m][d]

__device__ __forceinline__ float to_tf32(float x) { return wmma::__float_to_tf32(x); }
__device__ __forceinline__ uint32_t tf32u(float x) {
    uint32_t r; asm("cvt.rna.tf32.f32 %0, %1;" : "=r"(r) : "f"(x)); return r;
}
__device__ __forceinline__ float tf32f(float x) {
    float r; asm("cvt.rna.tf32.f32 %0, %1;" : "=f"(r) : "f"(x)); return r;
}

// ---------------- setup: theta (double pow, matches fp32 correctly-rounded) --
__global__ void setup_theta_kernel() {
    int i = threadIdx.x;  // 0..255
    double e = -2.0 * ((double)i - 1.0) / 512.0;
    g_theta[i] = (float)pow(10000.0, e);
}

// cos/sin table: angle computed exactly like the reference (fp32 pos * fp32 theta)
__global__ void setup_cs_kernel() {
    int pos = blockIdx.x;
    int i = threadIdx.x;
    float ang = (float)pos * g_theta[i];
    float s, c;
    sincosf(ang, &s, &c);
    g_cs[pos][i][0] = c;
    g_cs[pos][i][1] = s;
}

// ---------------- generic 64x64 tiled TF32 GEMM, 3 modes ---------------------
template<int MODE>
__global__ __launch_bounds__(128) void gemm64(
    const float* __restrict__ A,
    const float* __restrict__ B0,
    const float* __restrict__ B1,
    const float* __restrict__ B2,
    const float* __restrict__ bias,
    float* __restrict__ Cout)
{
    __shared__ __align__(32) float As[64][40];
    __shared__ __align__(32) float Bs[64][40];
    __shared__ __align__(32) float Csm[64][72];

    const int m0  = blockIdx.y * 64;
    const int n0g = blockIdx.x * 64;
    const int seg = n0g >> 9;        // which 512-col segment (q/k/v)
    const int n0  = n0g & 511;

    const float* Bp;
    const float* Ap;
    int lda;
    if (MODE == 0) {
        const float* Bsel = (seg == 0) ? B0 : ((seg == 1) ? B1 : B2);
        Bp = Bsel + (size_t)n0 * DIM;
        Ap = A + (size_t)m0 * DIM;  lda = DIM;
    } else if (MODE == 1) {
        Bp = B0 + (size_t)n0g * DIM;                 // in_proj_w rows n0g..n0g+63
        Ap = g_YR + (size_t)m0 * 1536 + seg * DIM;   // matching rotated segment
        lda = 1536;
    } else {
        Bp = B0 + (size_t)n0g * DIM;
        Ap = g_ctx + (size_t)m0 * DIM;  lda = DIM;
    }

    const int t = threadIdx.x;
    const int warp = t >> 5;
    const int wr = warp >> 1, wc = warp & 1;

    wmma::fragment<wmma::accumulator, 16, 16, 8, float> acc[2][2];
    #pragma unroll
    for (int i = 0; i < 2; i++)
        #pragma unroll
        for (int j = 0; j < 2; j++) wmma::fill_fragment(acc[i][j], 0.f);

    for (int k0 = 0; k0 < DIM; k0 += 32) {
        #pragma unroll
        for (int it = 0; it < 4; it++) {
            int idx = t + it * 128;        // 0..511 float4 slots
            int row = idx >> 3;
            int kc  = (idx & 7) << 2;
            float4 va = *reinterpret_cast<const float4*>(Ap + (size_t)row * lda + k0 + kc);
            As[row][kc+0] = to_tf32(va.x); As[row][kc+1] = to_tf32(va.y);
            As[row][kc+2] = to_tf32(va.z); As[row][kc+3] = to_tf32(va.w);
            float4 vb = *reinterpret_cast<const float4*>(Bp + (size_t)row * DIM + k0 + kc);
            Bs[row][kc+0] = to_tf32(vb.x); Bs[row][kc+1] = to_tf32(vb.y);
            Bs[row][kc+2] = to_tf32(vb.z); Bs[row][kc+3] = to_tf32(vb.w);
        }
        __syncthreads();
        #pragma unroll
        for (int kk = 0; kk < 32; kk += 8) {
            wmma::fragment<wmma::matrix_a, 16, 16, 8, wmma::precision::tf32, wmma::row_major> a0, a1;
            wmma::fragment<wmma::matrix_b, 16, 16, 8, wmma::precision::tf32, wmma::col_major> b0, b1;
            wmma::load_matrix_sync(a0, &As[wr*32     ][kk], 40);
            wmma::load_matrix_sync(a1, &As[wr*32 + 16][kk], 40);
            wmma::load_matrix_sync(b0, &Bs[wc*32     ][kk], 40);
            wmma::load_matrix_sync(b1, &Bs[wc*32 + 16][kk], 40);
            wmma::mma_sync(acc[0][0], a0, b0, acc[0][0]);
            wmma::mma_sync(acc[0][1], a0, b1, acc[0][1]);
            wmma::mma_sync(acc[1][0], a1, b0, acc[1][0]);
            wmma::mma_sync(acc[1][1], a1, b1, acc[1][1]);
        }
        __syncthreads();
    }

    wmma::store_matrix_sync(&Csm[wr*32     ][wc*32     ], acc[0][0], 72, wmma::mem_row_major);
    wmma::store_matrix_sync(&Csm[wr*32     ][wc*32 + 16], acc[0][1], 72, wmma::mem_row_major);
    wmma::store_matrix_sync(&Csm[wr*32 + 16][wc*32     ], acc[1][0], 72, wmma::mem_row_major);
    wmma::store_matrix_sync(&Csm[wr*32 + 16][wc*32 + 16], acc[1][1], 72, wmma::mem_row_major);
    __syncthreads();

    if (MODE == 0) {
        for (int idx = t; idx < 64 * 32; idx += 128) {
            int row = idx >> 5;
            int c   = (idx & 31) << 1;
            int gm  = m0 + row;
            int pos = gm & (SEQ - 1);
            int tp  = (n0 + c) >> 1;
            float e = Csm[row][c], o = Csm[row][c+1];
            float cc = g_cs[pos][tp][0], ss = g_cs[pos][tp][1];
            size_t base = (size_t)gm * 1536 + n0g + c;
            g_YR[base]     =  e * cc + o * ss;
            g_YR[base + 1] = -e * ss + o * cc;
        }
    } else if (MODE == 1) {
        for (int idx = t; idx < 64 * 64; idx += 128) {
            int row = idx >> 6;
            int c   = idx & 63;
            int gm  = m0 + row;
            float v = Csm[row][c] + bias[n0g + c];
            int batch = gm >> 11, pos = gm & (SEQ - 1);
            int jj   = n0 + c;
            int head = jj >> 6, dd = jj & 63;
            if (seg == 0) v *= 0.125f;  // fold attention scale 1/sqrt(64) into Q
            g_QKV[((((size_t)seg * BATCH + batch) * NH + head) * SEQ + pos) * HD + dd] = v;
        }
    } else {
        for (int idx = t; idx < 64 * 64; idx += 128) {
            int row = idx >> 6;
            int c   = idx & 63;
            int gm  = m0 + row;
            Cout[(size_t)gm * DIM + n0g + c] = Csm[row][c] + bias[n0g + c];
        }
    }
}

// ---------------- flash attention v2: PTX mma, register-resident Q/O ---------
// q-tile 128 rows, k-tile 64 keys, 256 threads (8 warps), warp owns 16-row stripe.
#define KS_LD 68
#define VS_LD 72
#define PS_LD 72
#define FLASH_SMEM ((64*KS_LD + 64*VS_LD + 128*PS_LD) * 4)

__device__ __forceinline__ void mma_tf32(float d[4], const uint32_t a[4],
                                         uint32_t b0, uint32_t b1) {
    asm volatile(
        "mma.sync.aligned.m16n8k8.row.col.f32.tf32.tf32.f32 "
        "{%0,%1,%2,%3}, {%4,%5,%6,%7}, {%8,%9}, {%0,%1,%2,%3};"
        : "+f"(d[0]), "+f"(d[1]), "+f"(d[2]), "+f"(d[3])
        : "r"(a[0]), "r"(a[1]), "r"(a[2]), "r"(a[3]), "r"(b0), "r"(b1));
}

__global__ void __launch_bounds__(256, 2) flash2_kernel()
{
    extern __shared__ float sm[];
    float* Ks = sm;                       // [64][KS_LD]
    float* Vs = Ks + 64 * KS_LD;          // [64][VS_LD]
    float* Ps = Vs + 64 * VS_LD;          // [128][PS_LD]

    const int bh = blockIdx.x;            // 0..63
    const int qt = 15 - blockIdx.y;       // heavy tiles first
    const int batch = bh >> 3, head = bh & 7;

    const int t = threadIdx.x;
    const int warp = t >> 5, lane = t & 31;
    const int g = lane >> 2, tg = lane & 3;
    const int base_r = warp * 16;              // row stripe within q tile
    const int qrow_lo = qt * 128 + base_r + g; // global seq row
    const int qrow_hi = qrow_lo + 8;

    const float* Qg = g_QKV + ((size_t)(0 * BATCH + batch) * NH + head) * SEQ * HD;
    const float* Kg = g_QKV + ((size_t)(1 * BATCH + batch) * NH + head) * SEQ * HD;
    const float* Vg = g_QKV + ((size_t)(2 * BATCH + batch) * NH + head) * SEQ * HD;

    // Q a-fragments: live in registers for the whole kt loop
    uint32_t Qa[8][4];
    #pragma unroll
    for (int kk = 0; kk < 8; kk++) {
        int c0 = kk * 8 + tg;
        Qa[kk][0] = tf32u(__ldg(Qg + (size_t)qrow_lo * HD + c0));
        Qa[kk][1] = tf32u(__ldg(Qg + (size_t)qrow_hi * HD + c0));
        Qa[kk][2] = tf32u(__ldg(Qg + (size_t)qrow_lo * HD + c0 + 4));
        Qa[kk][3] = tf32u(__ldg(Qg + (size_t)qrow_hi * HD + c0 + 4));
    }

    float O[8][4];
    #pragma unroll
    for (int n = 0; n < 8; n++) { O[n][0] = O[n][1] = O[n][2] = O[n][3] = 0.f; }
    float m_lo = -INFINITY, m_hi = -INFINITY, l_lo = 0.f, l_hi = 0.f;

    const int nkt = 2 * (qt + 1);
    for (int kt = 0; kt < nkt; kt++) {
        __syncthreads();   // previous-iteration Vs/Ks reads complete
        // cooperative K,V tile load (64x64 each)
        {
            const float4* K4 = reinterpret_cast<const float4*>(Kg + (size_t)kt * 64 * HD);
            const float4* V4 = reinterpret_cast<const float4*>(Vg + (size_t)kt * 64 * HD);
            #pragma unroll
            for (int it = 0; it < 4; it++) {
                int idx = t + it * 256;          // 0..1023 float4 slots
                int r = idx >> 4, c = (idx & 15) << 2;
                float4 kv = K4[idx];
                float* kd = &Ks[r * KS_LD + c];
                kd[0] = tf32f(kv.x); kd[1] = tf32f(kv.y); kd[2] = tf32f(kv.z); kd[3] = tf32f(kv.w);
                float4 vv = V4[idx];
                float* vd = &Vs[r * VS_LD + c];
                vd[0] = tf32f(vv.x); vd[1] = tf32f(vv.y); vd[2] = tf32f(vv.z); vd[3] = tf32f(vv.w);
            }
        }
        __syncthreads();

        // S = Q @ K^T   (16x64 per warp, in registers)
        float s[8][4];
        #pragma unroll
        for (int n = 0; n < 8; n++) { s[n][0] = s[n][1] = s[n][2] = s[n][3] = 0.f; }
        #pragma unroll
        for (int n = 0; n < 8; n++) {
            const float* kb = &Ks[(n * 8 + g) * KS_LD + tg];
            #pragma unroll
            for (int kk = 0; kk < 8; kk++) {
                uint32_t b0 = __float_as_uint(kb[kk * 8]);
                uint32_t b1 = __float_as_uint(kb[kk * 8 + 4]);
                mma_tf32(s[n], Qa[kk], b0, b1);
            }
        }

        // causal mask (only near the diagonal)
        if (kt * 64 + 63 > qt * 128 + base_r) {
            #pragma unroll
            for (int n = 0; n < 8; n++) {
                int gc0 = kt * 64 + n * 8 + 2 * tg;
                int gc1 = gc0 + 1;
                if (gc0 > qrow_lo) s[n][0] = -1e30f;
                if (gc1 > qrow_lo) s[n][1] = -1e30f;
                if (gc0 > qrow_hi) s[n][2] = -1e30f;
                if (gc1 > qrow_hi) s[n][3] = -1e30f;
            }
        }

        // online softmax, fully in registers
        float mx_lo = -1e30f, mx_hi = -1e30f;
        #pragma unroll
        for (int n = 0; n < 8; n++) {
            mx_lo = fmaxf(mx_lo, fmaxf(s[n][0], s[n][1]));
            mx_hi = fmaxf(mx_hi, fmaxf(s[n][2], s[n][3]));
        }
        mx_lo = fmaxf(mx_lo, __shfl_xor_sync(0xffffffffu, mx_lo, 1));
        mx_lo = fmaxf(mx_lo, __shfl_xor_sync(0xffffffffu, mx_lo, 2));
        mx_hi = fmaxf(mx_hi, __shfl_xor_sync(0xffffffffu, mx_hi, 1));
        mx_hi = fmaxf(mx_hi, __shfl_xor_sync(0xffffffffu, mx_hi, 2));

        float mnew_lo = fmaxf(m_lo, mx_lo);
        float mnew_hi = fmaxf(m_hi, mx_hi);
        float alpha_lo = __expf(m_lo - mnew_lo);
        float alpha_hi = __expf(m_hi - mnew_hi);
        m_lo = mnew_lo; m_hi = mnew_hi;

        float sum_lo = 0.f, sum_hi = 0.f;
        float* prow_lo = &Ps[(base_r + g) * PS_LD + 2 * tg];
        float* prow_hi = &Ps[(base_r + g + 8) * PS_LD + 2 * tg];
        #pragma unroll
        for (int n = 0; n < 8; n++) {
            float p0 = tf32f(__expf(s[n][0] - mnew_lo));
            float p1 = tf32f(__expf(s[n][1] - mnew_lo));
            float p2 = tf32f(__expf(s[n][2] - mnew_hi));
            float p3 = tf32f(__expf(s[n][3] - mnew_hi));
            sum_lo += p0 + p1;
            sum_hi += p2 + p3;
            *reinterpret_cast<float2*>(prow_lo + n * 8) = make_float2(p0, p1);
            *reinterpret_cast<float2*>(prow_hi + n * 8) = make_float2(p2, p3);
        }
        sum_lo += __shfl_xor_sync(0xffffffffu, sum_lo, 1);
        sum_lo += __shfl_xor_sync(0xffffffffu, sum_lo, 2);
        sum_hi += __shfl_xor_sync(0xffffffffu, sum_hi, 1);
        sum_hi += __shfl_xor_sync(0xffffffffu, sum_hi, 2);
        l_lo = l_lo * alpha_lo + sum_lo;
        l_hi = l_hi * alpha_hi + sum_hi;

        #pragma unroll
        for (int n = 0; n < 8; n++) {
            O[n][0] *= alpha_lo; O[n][1] *= alpha_lo;
            O[n][2] *= alpha_hi; O[n][3] *= alpha_hi;
        }
        __syncwarp();   // P stripe visible to this warp's loads

        // O += P @ V
        #pragma unroll
        for (int kk = 0; kk < 8; kk++) {
            uint32_t a[4];
            a[0] = __float_as_uint(Ps[(base_r + g    ) * PS_LD + kk * 8 + tg]);
            a[1] = __float_as_uint(Ps[(base_r + g + 8) * PS_LD + kk * 8 + tg]);
            a[2] = __float_as_uint(Ps[(base_r + g    ) * PS_LD + kk * 8 + tg + 4]);
            a[3] = __float_as_uint(Ps[(base_r + g + 8) * PS_LD + kk * 8 + tg + 4]);
            const float* vb = &Vs[(kk * 8 + tg) * VS_LD + g];
            #pragma unroll
            for (int n = 0; n < 8; n++) {
                uint32_t b0 = __float_as_uint(vb[n * 8]);
                uint32_t b1 = __float_as_uint(vb[n * 8 + 4 * VS_LD]);
                mma_tf32(O[n], a, b0, b1);
            }
        }
    }

    // epilogue: normalize and write straight to g_ctx
    float inv_lo = 1.f / l_lo, inv_hi = 1.f / l_hi;
    size_t row_lo = ((size_t)batch * SEQ + qrow_lo) * DIM + head * HD;
    size_t row_hi = row_lo + (size_t)8 * DIM;
    #pragma unroll
    for (int n = 0; n < 8; n++) {
        *reinterpret_cast<float2*>(&g_ctx[row_lo + n * 8 + 2 * tg]) =
            make_float2(O[n][0] * inv_lo, O[n][1] * inv_lo);
        *reinterpret_cast<float2*>(&g_ctx[row_hi + n * 8 + 2 * tg]) =
            make_float2(O[n][2] * inv_hi, O[n][3] * inv_hi);
    }
}

// ---------------- launch ----------------------------------------------------
extern "C" void kernel_launch(void* const* d_in, const int* in_sizes, int n_in,
                              void* d_out, int out_size)
{
    const float* x         = (const float*)d_in[0];
    const float* w_q       = (const float*)d_in[1];
    const float* w_k       = (const float*)d_in[2];
    const float* w_v       = (const float*)d_in[3];
    const float* in_proj_w = (const float*)d_in[4];
    const float* in_proj_b = (const float*)d_in[5];
    const float* out_w     = (const float*)d_in[6];
    const float* out_b     = (const float*)d_in[7];
    float* out = (float*)d_out;

    setup_theta_kernel<<<1, 256>>>();
    setup_cs_kernel<<<SEQ, 256>>>();

    // rot(x @ W^T) for q,k,v  (N = 1536)
    gemm64<0><<<dim3(24, 256), 128>>>(x, w_q, w_k, w_v, nullptr, nullptr);

    // in_proj + bias -> QKV [qkv][b][h][m][hd], Q pre-scaled
    gemm64<1><<<dim3(24, 256), 128>>>(nullptr, in_proj_w, nullptr, nullptr, in_proj_b, nullptr);

    // causal flash attention v2 -> g_ctx [b][m][d]
    cudaFuncSetAttribute(flash2_kernel, cudaFuncAttributeMaxDynamicSharedMemorySize, FLASH_SMEM);
    flash2_kernel<<<dim3(64, 16), 256, FLASH_SMEM>>>();

    // out projection + bias -> d_out
    gemm64<2><<<dim3(8, 256), 128>>>(nullptr, out_w, nullptr, nullptr, out_b, out);
}

// round 3
// speedup vs baseline: 2.6819x; 1.6053x over previous
#include <cuda_runtime.h>
#include <mma.h>
#include <math.h>
#include <stdint.h>

using namespace nvcuda;

#define BATCH 8
#define SEQ   2048
#define DIM   512
#define NH    8
#define HD    64
#define BM    (BATCH*SEQ)   // 16384

// ---------------- scratch (static device memory; no allocations allowed) ----
__device__ __align__(16) float g_theta[256];
__device__ __align__(16) float g_cs[SEQ][256][2];              // cos, sin per (pos, pair)
__device__ __align__(16) float g_YR[(size_t)BM * 1536];        // rot(x@Wq^T) | rot(x@Wk^T) | rot(x@Wv^T)
__device__ __align__(16) float g_QKV[(size_t)3 * BATCH * NH * SEQ * HD]; // [qkv][b][h][m][hd]
__device__ __align__(16) float g_ctx[(size_t)BM * DIM];        // attention output [b][m][d]

__device__ __forceinline__ uint32_t tf32u(float x) {
    uint32_t r; asm("cvt.rna.tf32.f32 %0, %1;" : "=r"(r) : "f"(x)); return r;
}
__device__ __forceinline__ float tf32f(float x) {
    float r; asm("cvt.rna.tf32.f32 %0, %1;" : "=f"(r) : "f"(x)); return r;
}
__device__ __forceinline__ uint32_t smem_u32(const void* p) {
    uint32_t a;
    asm("{ .reg .u64 t; cvta.to.shared.u64 t, %1; cvt.u32.u64 %0, t; }" : "=r"(a) : "l"(p));
    return a;
}
__device__ __forceinline__ void cp16(uint32_t dst, const void* src) {
    asm volatile("cp.async.cg.shared.global [%0], [%1], 16;" :: "r"(dst), "l"(src));
}
__device__ __forceinline__ void mma_tf32(float d[4], const uint32_t a[4],
                                         uint32_t b0, uint32_t b1) {
    asm volatile(
        "mma.sync.aligned.m16n8k8.row.col.f32.tf32.tf32.f32 "
        "{%0,%1,%2,%3}, {%4,%5,%6,%7}, {%8,%9}, {%0,%1,%2,%3};"
        : "+f"(d[0]), "+f"(d[1]), "+f"(d[2]), "+f"(d[3])
        : "r"(a[0]), "r"(a[1]), "r"(a[2]), "r"(a[3]), "r"(b0), "r"(b1));
}

// ---------------- setup ------------------------------------------------------
__global__ void setup_theta_kernel() {
    int i = threadIdx.x;  // 0..255
    double e = -2.0 * ((double)i - 1.0) / 512.0;
    g_theta[i] = (float)pow(10000.0, e);
}
__global__ void setup_cs_kernel() {
    int pos = blockIdx.x;
    int i = threadIdx.x;
    float ang = (float)pos * g_theta[i];
    float s, c;
    sincosf(ang, &s, &c);
    g_cs[pos][i][0] = c;
    g_cs[pos][i][1] = s;
}

// ---------------- 128x128-tile TF32 GEMM, cp.async double-buffered -----------
// MODE 0: YR = rope(x @ {w_q,w_k,w_v}^T),  N=1536
// MODE 1: QKV = YR @ in_proj_w^T + b,      N=1536, scatter + Q scale
// MODE 2: out = g_ctx @ out_w^T + out_b,   N=512
#define GLDA 36
#define GTILE (128 * GLDA)           // floats per matrix tile
#define GEMM_SMEM (2 * 2 * GTILE * 4) // 73728 bytes

template<int MODE>
__global__ __launch_bounds__(128) void gemm128(
    const float* __restrict__ A,
    const float* __restrict__ B0,
    const float* __restrict__ B1,
    const float* __restrict__ B2,
    const float* __restrict__ bias,
    float* __restrict__ Cout)
{
    extern __shared__ float sm[];

    const int m0  = blockIdx.y * 128;
    const int n0g = blockIdx.x * 128;
    const int seg = n0g >> 9;          // q/k/v segment (blocks never straddle)
    const int n0  = n0g & 511;

    const float* Ap;
    const float* Bp;
    int lda;
    if (MODE == 0) {
        const float* Bsel = (seg == 0) ? B0 : ((seg == 1) ? B1 : B2);
        Bp = Bsel + (size_t)n0 * DIM;
        Ap = A + (size_t)m0 * DIM;  lda = DIM;
    } else if (MODE == 1) {
        Bp = B0 + (size_t)n0g * DIM;
        Ap = g_YR + (size_t)m0 * 1536 + seg * DIM;  lda = 1536;
    } else {
        Bp = B0 + (size_t)n0g * DIM;
        Ap = g_ctx + (size_t)m0 * DIM;  lda = DIM;
    }

    const int t    = threadIdx.x;
    const int warp = t >> 5, lane = t & 31;
    const int wr   = warp >> 1, wc = warp & 1;      // 2x2 warp grid, 64x64 each
    const int g    = lane >> 2, tg = lane & 3;

    const uint32_t sbase = smem_u32(sm);
    // buffers: [buf][A 4608][B 4608]
    const int ld_row = t >> 3;            // 0..15 base row
    const int ld_c4  = (t & 7) << 2;      // 0,4,...,28

    float acc[4][8][4];
    #pragma unroll
    for (int mi = 0; mi < 4; mi++)
        #pragma unroll
        for (int ni = 0; ni < 8; ni++)
            #pragma unroll
            for (int r = 0; r < 4; r++) acc[mi][ni][r] = 0.f;

    // ---- async tile copy: 8 rows-of-16 iterations each for A and B ----
    auto issue_tile = [&](int buf, int k0) {
        uint32_t abase = sbase + (uint32_t)buf * 2 * GTILE * 4;
        uint32_t bbase = abase + GTILE * 4;
        #pragma unroll
        for (int it = 0; it < 8; it++) {
            int row = ld_row + it * 16;
            cp16(abase + (row * GLDA + ld_c4) * 4, Ap + (size_t)row * lda + k0 + ld_c4);
            cp16(bbase + (row * GLDA + ld_c4) * 4, Bp + (size_t)row * DIM + k0 + ld_c4);
        }
        asm volatile("cp.async.commit_group;");
    };

    issue_tile(0, 0);

    #pragma unroll 1
    for (int kt = 0; kt < 16; kt++) {
        asm volatile("cp.async.wait_group 0;");
        __syncthreads();
        if (kt < 15) issue_tile((kt + 1) & 1, (kt + 1) * 32);

        const float* As = sm + (kt & 1) * 2 * GTILE;
        const float* Bs = As + GTILE;
        const float* Abase = As + (wr * 64 + g) * GLDA + tg;
        const float* Bbase = Bs + (wc * 64 + g) * GLDA + tg;

        #pragma unroll
        for (int ks = 0; ks < 4; ks++) {
            const int kof = ks * 8;
            uint32_t a[4][4];
            #pragma unroll
            for (int mi = 0; mi < 4; mi++) {
                const float* ap = Abase + mi * 16 * GLDA + kof;
                a[mi][0] = tf32u(ap[0]);
                a[mi][1] = tf32u(ap[8 * GLDA]);
                a[mi][2] = tf32u(ap[4]);
                a[mi][3] = tf32u(ap[8 * GLDA + 4]);
            }
            uint32_t b[8][2];
            #pragma unroll
            for (int ni = 0; ni < 8; ni++) {
                const float* bp = Bbase + ni * 8 * GLDA + kof;
                b[ni][0] = tf32u(bp[0]);
                b[ni][1] = tf32u(bp[4]);
            }
            #pragma unroll
            for (int mi = 0; mi < 4; mi++)
                #pragma unroll
                for (int ni = 0; ni < 8; ni++)
                    mma_tf32(acc[mi][ni], a[mi], b[ni][0], b[ni][1]);
        }
        __syncthreads();
    }

    // ---- fused epilogue straight from registers ----
    const int gm_base = m0 + wr * 64;
    const int gn_base = n0g + wc * 64;

    #pragma unroll
    for (int mi = 0; mi < 4; mi++) {
        #pragma unroll
        for (int h = 0; h < 2; h++) {
            const int gm  = gm_base + mi * 16 + g + h * 8;
            const int pos = gm & (SEQ - 1);
            #pragma unroll
            for (int ni = 0; ni < 8; ni++) {
                float c0 = acc[mi][ni][2 * h];
                float c1 = acc[mi][ni][2 * h + 1];
                const int col = gn_base + ni * 8 + 2 * tg;
                if (MODE == 0) {
                    const int tp = (col & 511) >> 1;
                    float2 cs = *reinterpret_cast<const float2*>(&g_cs[pos][tp][0]);
                    float2 r;
                    r.x =  c0 * cs.x + c1 * cs.y;
                    r.y = -c0 * cs.y + c1 * cs.x;
                    *reinterpret_cast<float2*>(&g_YR[(size_t)gm * 1536 + col]) = r;
                } else if (MODE == 1) {
                    float2 bb = *reinterpret_cast<const float2*>(&bias[col]);
                    float v0 = c0 + bb.x, v1 = c1 + bb.y;
                    if (seg == 0) { v0 *= 0.125f; v1 *= 0.125f; }
                    const int batch = gm >> 11;
                    const int head  = (col & 511) >> 6;
                    const int dd    = col & 63;
                    size_t o = (((size_t)(seg * BATCH + batch) * NH + head) * SEQ + pos) * HD + dd;
                    *reinterpret_cast<float2*>(&g_QKV[o]) = make_float2(v0, v1);
                } else {
                    float2 bb = *reinterpret_cast<const float2*>(&bias[col]);
                    *reinterpret_cast<float2*>(&Cout[(size_t)gm * DIM + col]) =
                        make_float2(c0 + bb.x, c1 + bb.y);
                }
            }
        }
    }
}

// ---------------- flash attention v2: PTX mma, register-resident Q/O ---------
#define KS_LD 68
#define VS_LD 72
#define PS_LD 72
#define FLASH_SMEM ((64*KS_LD + 64*VS_LD + 128*PS_LD) * 4)

__global__ void __launch_bounds__(256, 2) flash2_kernel()
{
    extern __shared__ float sm[];
    float* Ks = sm;                       // [64][KS_LD]
    float* Vs = Ks + 64 * KS_LD;          // [64][VS_LD]
    float* Ps = Vs + 64 * VS_LD;          // [128][PS_LD]

    const int bh = blockIdx.x;            // 0..63
    const int qt = 15 - blockIdx.y;       // heavy tiles first
    const int batch = bh >> 3, head = bh & 7;

    const int t = threadIdx.x;
    const int warp = t >> 5, lane = t & 31;
    const int g = lane >> 2, tg = lane & 3;
    const int base_r = warp * 16;
    const int qrow_lo = qt * 128 + base_r + g;
    const int qrow_hi = qrow_lo + 8;

    const float* Qg = g_QKV + ((size_t)(0 * BATCH + batch) * NH + head) * SEQ * HD;
    const float* Kg = g_QKV + ((size_t)(1 * BATCH + batch) * NH + head) * SEQ * HD;
    const float* Vg = g_QKV + ((size_t)(2 * BATCH + batch) * NH + head) * SEQ * HD;

    uint32_t Qa[8][4];
    #pragma unroll
    for (int kk = 0; kk < 8; kk++) {
        int c0 = kk * 8 + tg;
        Qa[kk][0] = tf32u(__ldg(Qg + (size_t)qrow_lo * HD + c0));
        Qa[kk][1] = tf32u(__ldg(Qg + (size_t)qrow_hi * HD + c0));
        Qa[kk][2] = tf32u(__ldg(Qg + (size_t)qrow_lo * HD + c0 + 4));
        Qa[kk][3] = tf32u(__ldg(Qg + (size_t)qrow_hi * HD + c0 + 4));
    }

    float O[8][4];
    #pragma unroll
    for (int n = 0; n < 8; n++) { O[n][0] = O[n][1] = O[n][2] = O[n][3] = 0.f; }
    float m_lo = -INFINITY, m_hi = -INFINITY, l_lo = 0.f, l_hi = 0.f;

    const int nkt = 2 * (qt + 1);
    for (int kt = 0; kt < nkt; kt++) {
        __syncthreads();
        {
            const float4* K4 = reinterpret_cast<const float4*>(Kg + (size_t)kt * 64 * HD);
            const float4* V4 = reinterpret_cast<const float4*>(Vg + (size_t)kt * 64 * HD);
            #pragma unroll
            for (int it = 0; it < 4; it++) {
                int idx = t + it * 256;
                int r = idx >> 4, c = (idx & 15) << 2;
                float4 kv = K4[idx];
                float* kd = &Ks[r * KS_LD + c];
                kd[0] = tf32f(kv.x); kd[1] = tf32f(kv.y); kd[2] = tf32f(kv.z); kd[3] = tf32f(kv.w);
                float4 vv = V4[idx];
                float* vd = &Vs[r * VS_LD + c];
                vd[0] = tf32f(vv.x); vd[1] = tf32f(vv.y); vd[2] = tf32f(vv.z); vd[3] = tf32f(vv.w);
            }
        }
        __syncthreads();

        float s[8][4];
        #pragma unroll
        for (int n = 0; n < 8; n++) { s[n][0] = s[n][1] = s[n][2] = s[n][3] = 0.f; }
        #pragma unroll
        for (int n = 0; n < 8; n++) {
            const float* kb = &Ks[(n * 8 + g) * KS_LD + tg];
            #pragma unroll
            for (int kk = 0; kk < 8; kk++) {
                uint32_t b0 = __float_as_uint(kb[kk * 8]);
                uint32_t b1 = __float_as_uint(kb[kk * 8 + 4]);
                mma_tf32(s[n], Qa[kk], b0, b1);
            }
        }

        if (kt * 64 + 63 > qt * 128 + base_r) {
            #pragma unroll
            for (int n = 0; n < 8; n++) {
                int gc0 = kt * 64 + n * 8 + 2 * tg;
                int gc1 = gc0 + 1;
                if (gc0 > qrow_lo) s[n][0] = -1e30f;
                if (gc1 > qrow_lo) s[n][1] = -1e30f;
                if (gc0 > qrow_hi) s[n][2] = -1e30f;
                if (gc1 > qrow_hi) s[n][3] = -1e30f;
            }
        }

        float mx_lo = -1e30f, mx_hi = -1e30f;
        #pragma unroll
        for (int n = 0; n < 8; n++) {
            mx_lo = fmaxf(mx_lo, fmaxf(s[n][0], s[n][1]));
            mx_hi = fmaxf(mx_hi, fmaxf(s[n][2], s[n][3]));
        }
        mx_lo = fmaxf(mx_lo, __shfl_xor_sync(0xffffffffu, mx_lo, 1));
        mx_lo = fmaxf(mx_lo, __shfl_xor_sync(0xffffffffu, mx_lo, 2));
        mx_hi = fmaxf(mx_hi, __shfl_xor_sync(0xffffffffu, mx_hi, 1));
        mx_hi = fmaxf(mx_hi, __shfl_xor_sync(0xffffffffu, mx_hi, 2));

        float mnew_lo = fmaxf(m_lo, mx_lo);
        float mnew_hi = fmaxf(m_hi, mx_hi);
        float alpha_lo = __expf(m_lo - mnew_lo);
        float alpha_hi = __expf(m_hi - mnew_hi);
        m_lo = mnew_lo; m_hi = mnew_hi;

        float sum_lo = 0.f, sum_hi = 0.f;
        float* prow_lo = &Ps[(base_r + g) * PS_LD + 2 * tg];
        float* prow_hi = &Ps[(base_r + g + 8) * PS_LD + 2 * tg];
        #pragma unroll
        for (int n = 0; n < 8; n++) {
            float p0 = tf32f(__expf(s[n][0] - mnew_lo));
            float p1 = tf32f(__expf(s[n][1] - mnew_lo));
            float p2 = tf32f(__expf(s[n][2] - mnew_hi));
            float p3 = tf32f(__expf(s[n][3] - mnew_hi));
            sum_lo += p0 + p1;
            sum_hi += p2 + p3;
            *reinterpret_cast<float2*>(prow_lo + n * 8) = make_float2(p0, p1);
            *reinterpret_cast<float2*>(prow_hi + n * 8) = make_float2(p2, p3);
        }
        sum_lo += __shfl_xor_sync(0xffffffffu, sum_lo, 1);
        sum_lo += __shfl_xor_sync(0xffffffffu, sum_lo, 2);
        sum_hi += __shfl_xor_sync(0xffffffffu, sum_hi, 1);
        sum_hi += __shfl_xor_sync(0xffffffffu, sum_hi, 2);
        l_lo = l_lo * alpha_lo + sum_lo;
        l_hi = l_hi * alpha_hi + sum_hi;

        #pragma unroll
        for (int n = 0; n < 8; n++) {
            O[n][0] *= alpha_lo; O[n][1] *= alpha_lo;
            O[n][2] *= alpha_hi; O[n][3] *= alpha_hi;
        }
        __syncwarp();

        #pragma unroll
        for (int kk = 0; kk < 8; kk++) {
            uint32_t a[4];
            a[0] = __float_as_uint(Ps[(base_r + g    ) * PS_LD + kk * 8 + tg]);
            a[1] = __float_as_uint(Ps[(base_r + g + 8) * PS_LD + kk * 8 + tg]);
            a[2] = __float_as_uint(Ps[(base_r + g    ) * PS_LD + kk * 8 + tg + 4]);
            a[3] = __float_as_uint(Ps[(base_r + g + 8) * PS_LD + kk * 8 + tg + 4]);
            const float* vb = &Vs[(kk * 8 + tg) * VS_LD + g];
            #pragma unroll
            for (int n = 0; n < 8; n++) {
                uint32_t b0 = __float_as_uint(vb[n * 8]);
                uint32_t b1 = __float_as_uint(vb[n * 8 + 4 * VS_LD]);
                mma_tf32(O[n], a, b0, b1);
            }
        }
    }

    float inv_lo = 1.f / l_lo, inv_hi = 1.f / l_hi;
    size_t row_lo = ((size_t)batch * SEQ + qrow_lo) * DIM + head * HD;
    size_t row_hi = row_lo + (size_t)8 * DIM;
    #pragma unroll
    for (int n = 0; n < 8; n++) {
        *reinterpret_cast<float2*>(&g_ctx[row_lo + n * 8 + 2 * tg]) =
            make_float2(O[n][0] * inv_lo, O[n][1] * inv_lo);
        *reinterpret_cast<float2*>(&g_ctx[row_hi + n * 8 + 2 * tg]) =
            make_float2(O[n][2] * inv_hi, O[n][3] * inv_hi);
    }
}

// ---------------- launch ----------------------------------------------------
extern "C" void kernel_launch(void* const* d_in, const int* in_sizes, int n_in,
                              void* d_out, int out_size)
{
    const float* x         = (const float*)d_in[0];
    const float* w_q       = (const float*)d_in[1];
    const float* w_k       = (const float*)d_in[2];
    const float* w_v       = (const float*)d_in[3];
    const float* in_proj_w = (const float*)d_in[4];
    const float* in_proj_b = (const float*)d_in[5];
    const float* out_w     = (const float*)d_in[6];
    const float* out_b     = (const float*)d_in[7];
    float* out = (float*)d_out;

    setup_theta_kernel<<<1, 256>>>();
    setup_cs_kernel<<<SEQ, 256>>>();

    cudaFuncSetAttribute(gemm128<0>, cudaFuncAttributeMaxDynamicSharedMemorySize, GEMM_SMEM);
    cudaFuncSetAttribute(gemm128<1>, cudaFuncAttributeMaxDynamicSharedMemorySize, GEMM_SMEM);
    cudaFuncSetAttribute(gemm128<2>, cudaFuncAttributeMaxDynamicSharedMemorySize, GEMM_SMEM);

    // rot(x @ W^T) for q,k,v  (N = 1536)
    gemm128<0><<<dim3(12, 128), 128, GEMM_SMEM>>>(x, w_q, w_k, w_v, nullptr, nullptr);

    // in_proj + bias -> QKV [qkv][b][h][m][hd], Q pre-scaled
    gemm128<1><<<dim3(12, 128), 128, GEMM_SMEM>>>(nullptr, in_proj_w, nullptr, nullptr, in_proj_b, nullptr);

    // causal flash attention v2 -> g_ctx [b][m][d]
    cudaFuncSetAttribute(flash2_kernel, cudaFuncAttributeMaxDynamicSharedMemorySize, FLASH_SMEM);
    flash2_kernel<<<dim3(64, 16), 256, FLASH_SMEM>>>();

    // out projection + bias -> d_out
    gemm128<2><<<dim3(4, 128), 128, GEMM_SMEM>>>(nullptr, out_w, nullptr, nullptr, out_b, out);
}

// round 5
// speedup vs baseline: 2.7117x; 1.0111x over previous
#include <cuda_runtime.h>
#include <math.h>
#include <stdint.h>

#define BATCH 8
#define SEQ   2048
#define DIM   512
#define NH    8
#define HD    64
#define BM    (BATCH*SEQ)   // 16384

// ---------------- scratch (static device memory; no allocations allowed) ----
__device__ __align__(16) float g_theta[256];
__device__ __align__(16) float g_cs[SEQ][256][2];              // cos, sin per (pos, pair)
__device__ __align__(16) float g_YR[(size_t)BM * 1536];        // rot(x@Wq^T) | rot(x@Wk^T) | rot(x@Wv^T)
__device__ __align__(16) float g_QKV[(size_t)3 * BATCH * NH * SEQ * HD]; // [qkv][b][h][m][hd], tf32-rounded
__device__ __align__(16) float g_ctx[(size_t)BM * DIM];        // attention output [b][m][d]

__device__ __forceinline__ uint32_t tf32u(float x) {
    uint32_t r; asm("cvt.rna.tf32.f32 %0, %1;" : "=r"(r) : "f"(x)); return r;
}
__device__ __forceinline__ float tf32f(float x) {
    float r; asm("cvt.rna.tf32.f32 %0, %1;" : "=f"(r) : "f"(x)); return r;
}
__device__ __forceinline__ uint32_t smem_u32(const void* p) {
    uint32_t a;
    asm("{ .reg .u64 t; cvta.to.shared.u64 t, %1; cvt.u32.u64 %0, t; }" : "=r"(a) : "l"(p));
    return a;
}
__device__ __forceinline__ void cp16(uint32_t dst, const void* src) {
    asm volatile("cp.async.cg.shared.global [%0], [%1], 16;" :: "r"(dst), "l"(src));
}
__device__ __forceinline__ void mma_tf32(float d[4], const uint32_t a[4],
                                         uint32_t b0, uint32_t b1) {
    asm volatile(
        "mma.sync.aligned.m16n8k8.row.col.f32.tf32.tf32.f32 "
        "{%0,%1,%2,%3}, {%4,%5,%6,%7}, {%8,%9}, {%0,%1,%2,%3};"
        : "+f"(d[0]), "+f"(d[1]), "+f"(d[2]), "+f"(d[3])
        : "r"(a[0]), "r"(a[1]), "r"(a[2]), "r"(a[3]), "r"(b0), "r"(b1));
}

// ---------------- setup ------------------------------------------------------
__global__ void setup_theta_kernel() {
    int i = threadIdx.x;  // 0..255
    double e = -2.0 * ((double)i - 1.0) / 512.0;
    g_theta[i] = (float)pow(10000.0, e);
}
__global__ void setup_cs_kernel() {
    int pos = blockIdx.x;
    int i = threadIdx.x;
    float ang = (float)pos * g_theta[i];
    float s, c;
    sincosf(ang, &s, &c);
    g_cs[pos][i][0] = c;
    g_cs[pos][i][1] = s;
}

// ---------------- 128x128-tile TF32 GEMM, 256 threads, cp.async 2-stage ------
// MODE 0: YR = rope(x @ {w_q,w_k,w_v}^T),  N=1536
// MODE 1: QKV = YR @ in_proj_w^T + b,      N=1536, scatter + Q scale + tf32 round
// MODE 2: out = g_ctx @ out_w^T + out_b,   N=512
#define GLDA 36
#define GTILE (128 * GLDA)            // floats per matrix tile
#define GEMM_SMEM (2 * 2 * GTILE * 4) // 73728 bytes

template<int MODE>
__global__ __launch_bounds__(256, 2) void gemm128(
    const float* __restrict__ A,
    const float* __restrict__ B0,
    const float* __restrict__ B1,
    const float* __restrict__ B2,
    const float* __restrict__ bias,
    float* __restrict__ Cout)
{
    extern __shared__ float sm[];

    const int m0  = blockIdx.y * 128;
    const int n0g = blockIdx.x * 128;
    const int seg = n0g >> 9;          // q/k/v segment (blocks never straddle)
    const int n0  = n0g & 511;

    const float* Ap;
    const float* Bp;
    int lda;
    if (MODE == 0) {
        const float* Bsel = (seg == 0) ? B0 : ((seg == 1) ? B1 : B2);
        Bp = Bsel + (size_t)n0 * DIM;
        Ap = A + (size_t)m0 * DIM;  lda = DIM;
    } else if (MODE == 1) {
        Bp = B0 + (size_t)n0g * DIM;
        Ap = g_YR + (size_t)m0 * 1536 + seg * DIM;  lda = 1536;
    } else {
        Bp = B0 + (size_t)n0g * DIM;
        Ap = g_ctx + (size_t)m0 * DIM;  lda = DIM;
    }

    const int t    = threadIdx.x;
    const int warp = t >> 5, lane = t & 31;
    const int wr   = warp >> 2, wc = warp & 3;      // 2x4 warp grid, 64x32 each
    const int g    = lane >> 2, tg = lane & 3;

    const uint32_t sbase = smem_u32(sm);
    const int ld_row = t >> 3;            // 0..31 base row
    const int ld_c4  = (t & 7) << 2;      // 0,4,...,28

    float acc[4][4][4];
    #pragma unroll
    for (int mi = 0; mi < 4; mi++)
        #pragma unroll
        for (int ni = 0; ni < 4; ni++)
            #pragma unroll
            for (int r = 0; r < 4; r++) acc[mi][ni][r] = 0.f;

    // ---- async tile copy: 4 rows-of-32 iterations each for A and B ----
    auto issue_tile = [&](int buf, int k0) {
        uint32_t abase = sbase + (uint32_t)buf * 2 * GTILE * 4;
        uint32_t bbase = abase + GTILE * 4;
        #pragma unroll
        for (int it = 0; it < 4; it++) {
            int row = ld_row + it * 32;
            cp16(abase + (row * GLDA + ld_c4) * 4, Ap + (size_t)row * lda + k0 + ld_c4);
            cp16(bbase + (row * GLDA + ld_c4) * 4, Bp + (size_t)row * DIM + k0 + ld_c4);
        }
        asm volatile("cp.async.commit_group;");
    };

    issue_tile(0, 0);

    #pragma unroll 1
    for (int kt = 0; kt < 16; kt++) {
        asm volatile("cp.async.wait_group 0;");
        __syncthreads();
        if (kt < 15) issue_tile((kt + 1) & 1, (kt + 1) * 32);

        const float* As = sm + (kt & 1) * 2 * GTILE;
        const float* Bs = As + GTILE;
        const float* Abase = As + (wr * 64 + g) * GLDA + tg;
        const float* Bbase = Bs + (wc * 32 + g) * GLDA + tg;

        #pragma unroll
        for (int ks = 0; ks < 4; ks++) {
            const int kof = ks * 8;
            uint32_t a[4][4];
            #pragma unroll
            for (int mi = 0; mi < 4; mi++) {
                const float* ap = Abase + mi * 16 * GLDA + kof;
                a[mi][0] = tf32u(ap[0]);
                a[mi][1] = tf32u(ap[8 * GLDA]);
                a[mi][2] = tf32u(ap[4]);
                a[mi][3] = tf32u(ap[8 * GLDA + 4]);
            }
            uint32_t b[4][2];
            #pragma unroll
            for (int ni = 0; ni < 4; ni++) {
                const float* bp = Bbase + ni * 8 * GLDA + kof;
                b[ni][0] = tf32u(bp[0]);
                b[ni][1] = tf32u(bp[4]);
            }
            #pragma unroll
            for (int mi = 0; mi < 4; mi++)
                #pragma unroll
                for (int ni = 0; ni < 4; ni++)
                    mma_tf32(acc[mi][ni], a[mi], b[ni][0], b[ni][1]);
        }
        __syncthreads();
    }

    // ---- fused epilogue straight from registers ----
    const int gm_base = m0 + wr * 64;
    const int gn_base = n0g + wc * 32;

    #pragma unroll
    for (int mi = 0; mi < 4; mi++) {
        #pragma unroll
        for (int h = 0; h < 2; h++) {
            const int gm  = gm_base + mi * 16 + g + h * 8;
            const int pos = gm & (SEQ - 1);
            #pragma unroll
            for (int ni = 0; ni < 4; ni++) {
                float c0 = acc[mi][ni][2 * h];
                float c1 = acc[mi][ni][2 * h + 1];
                const int col = gn_base + ni * 8 + 2 * tg;
                if (MODE == 0) {
                    const int tp = (col & 511) >> 1;
                    float2 cs = *reinterpret_cast<const float2*>(&g_cs[pos][tp][0]);
                    float2 r;
                    r.x =  c0 * cs.x + c1 * cs.y;
                    r.y = -c0 * cs.y + c1 * cs.x;
                    *reinterpret_cast<float2*>(&g_YR[(size_t)gm * 1536 + col]) = r;
                } else if (MODE == 1) {
                    float2 bb = *reinterpret_cast<const float2*>(&bias[col]);
                    float v0 = c0 + bb.x, v1 = c1 + bb.y;
                    if (seg == 0) { v0 *= 0.125f; v1 *= 0.125f; }
                    v0 = tf32f(v0); v1 = tf32f(v1);   // pre-round for flash
                    const int batch = gm >> 11;
                    const int head  = (col & 511) >> 6;
                    const int dd    = col & 63;
                    size_t o = (((size_t)(seg * BATCH + batch) * NH + head) * SEQ + pos) * HD + dd;
                    *reinterpret_cast<float2*>(&g_QKV[o]) = make_float2(v0, v1);
                } else {
                    float2 bb = *reinterpret_cast<const float2*>(&bias[col]);
                    *reinterpret_cast<float2*>(&Cout[(size_t)gm * DIM + col]) =
                        make_float2(c0 + bb.x, c1 + bb.y);
                }
            }
        }
    }
}

// ---------------- flash attention v3: cp.async double-buffered K/V -----------
#define KS_LD 68
#define VS_LD 72
#define PS_LD 72
#define FLASH_SMEM ((2*64*KS_LD + 2*64*VS_LD + 128*PS_LD) * 4)

__global__ void __launch_bounds__(256, 2) flash2_kernel()
{
    extern __shared__ float sm[];
    float* Ksb = sm;                          // [2][64][KS_LD]
    float* Vsb = Ksb + 2 * 64 * KS_LD;        // [2][64][VS_LD]
    float* Ps  = Vsb + 2 * 64 * VS_LD;        // [128][PS_LD]

    const int bh = blockIdx.x;            // 0..63
    const int qt = 15 - blockIdx.y;       // heavy tiles first
    const int batch = bh >> 3, head = bh & 7;

    const int t = threadIdx.x;
    const int warp = t >> 5, lane = t & 31;
    const int g = lane >> 2, tg = lane & 3;
    const int base_r = warp * 16;
    const int qrow_lo = qt * 128 + base_r + g;
    const int qrow_hi = qrow_lo + 8;

    const float* Qg = g_QKV + ((size_t)(0 * BATCH + batch) * NH + head) * SEQ * HD;
    const float* Kg = g_QKV + ((size_t)(1 * BATCH + batch) * NH + head) * SEQ * HD;
    const float* Vg = g_QKV + ((size_t)(2 * BATCH + batch) * NH + head) * SEQ * HD;

    const uint32_t ksb = smem_u32(Ksb);
    const uint32_t vsb = smem_u32(Vsb);

    // full 64x64 tile copy: 4 iterations x 256 threads x 1 float4
    auto issue_kv = [&](int kt) {
        int buf = kt & 1;
        #pragma unroll
        for (int it = 0; it < 4; it++) {
            int idx = t + it * 256;            // 0..1023 float4 slots
            int r = idx >> 4, c = (idx & 15) << 2;
            cp16(ksb + (uint32_t)(buf * 64 * KS_LD + r * KS_LD + c) * 4,
                 Kg + (size_t)kt * 4096 + (size_t)idx * 4);
            cp16(vsb + (uint32_t)(buf * 64 * VS_LD + r * VS_LD + c) * 4,
                 Vg + (size_t)kt * 4096 + (size_t)idx * 4);
        }
        asm volatile("cp.async.commit_group;");
    };

    const int nkt = 2 * (qt + 1);
    issue_kv(0);

    // Q a-fragments (pre-rounded tf32 in g_QKV): registers for whole loop
    uint32_t Qa[8][4];
    #pragma unroll
    for (int kk = 0; kk < 8; kk++) {
        int c0 = kk * 8 + tg;
        Qa[kk][0] = __float_as_uint(__ldg(Qg + (size_t)qrow_lo * HD + c0));
        Qa[kk][1] = __float_as_uint(__ldg(Qg + (size_t)qrow_hi * HD + c0));
        Qa[kk][2] = __float_as_uint(__ldg(Qg + (size_t)qrow_lo * HD + c0 + 4));
        Qa[kk][3] = __float_as_uint(__ldg(Qg + (size_t)qrow_hi * HD + c0 + 4));
    }

    float O[8][4];
    #pragma unroll
    for (int n = 0; n < 8; n++) { O[n][0] = O[n][1] = O[n][2] = O[n][3] = 0.f; }
    float m_lo = -INFINITY, m_hi = -INFINITY, l_lo = 0.f, l_hi = 0.f;

    #pragma unroll 1
    for (int kt = 0; kt < nkt; kt++) {
        asm volatile("cp.async.wait_group 0;");
        __syncthreads();
        if (kt + 1 < nkt) issue_kv(kt + 1);

        const float* Ks = Ksb + (kt & 1) * 64 * KS_LD;
        const float* Vs = Vsb + (kt & 1) * 64 * VS_LD;

        // S = Q @ K^T   (16x64 per warp, in registers)
        float s[8][4];
        #pragma unroll
        for (int n = 0; n < 8; n++) { s[n][0] = s[n][1] = s[n][2] = s[n][3] = 0.f; }
        #pragma unroll
        for (int n = 0; n < 8; n++) {
            const float* kb = &Ks[(n * 8 + g) * KS_LD + tg];
            #pragma unroll
            for (int kk = 0; kk < 8; kk++) {
                uint32_t b0 = __float_as_uint(kb[kk * 8]);
                uint32_t b1 = __float_as_uint(kb[kk * 8 + 4]);
                mma_tf32(s[n], Qa[kk], b0, b1);
            }
        }

        if (kt * 64 + 63 > qt * 128 + base_r) {
            #pragma unroll
            for (int n = 0; n < 8; n++) {
                int gc0 = kt * 64 + n * 8 + 2 * tg;
                int gc1 = gc0 + 1;
                if (gc0 > qrow_lo) s[n][0] = -1e30f;
                if (gc1 > qrow_lo) s[n][1] = -1e30f;
                if (gc0 > qrow_hi) s[n][2] = -1e30f;
                if (gc1 > qrow_hi) s[n][3] = -1e30f;
            }
        }

        float mx_lo = -1e30f, mx_hi = -1e30f;
        #pragma unroll
        for (int n = 0; n < 8; n++) {
            mx_lo = fmaxf(mx_lo, fmaxf(s[n][0], s[n][1]));
            mx_hi = fmaxf(mx_hi, fmaxf(s[n][2], s[n][3]));
        }
        mx_lo = fmaxf(mx_lo, __shfl_xor_sync(0xffffffffu, mx_lo, 1));
        mx_lo = fmaxf(mx_lo, __shfl_xor_sync(0xffffffffu, mx_lo, 2));
        mx_hi = fmaxf(mx_hi, __shfl_xor_sync(0xffffffffu, mx_hi, 1));
        mx_hi = fmaxf(mx_hi, __shfl_xor_sync(0xffffffffu, mx_hi, 2));

        float mnew_lo = fmaxf(m_lo, mx_lo);
        float mnew_hi = fmaxf(m_hi, mx_hi);
        float alpha_lo = __expf(m_lo - mnew_lo);
        float alpha_hi = __expf(m_hi - mnew_hi);
        m_lo = mnew_lo; m_hi = mnew_hi;

        float sum_lo = 0.f, sum_hi = 0.f;
        float* prow_lo = &Ps[(base_r + g) * PS_LD + 2 * tg];
        float* prow_hi = &Ps[(base_r + g + 8) * PS_LD + 2 * tg];
        #pragma unroll
        for (int n = 0; n < 8; n++) {
            float p0 = tf32f(__expf(s[n][0] - mnew_lo));
            float p1 = tf32f(__expf(s[n][1] - mnew_lo));
            float p2 = tf32f(__expf(s[n][2] - mnew_hi));
            float p3 = tf32f(__expf(s[n][3] - mnew_hi));
            sum_lo += p0 + p1;
            sum_hi += p2 + p3;
            *reinterpret_cast<float2*>(prow_lo + n * 8) = make_float2(p0, p1);
            *reinterpret_cast<float2*>(prow_hi + n * 8) = make_float2(p2, p3);
        }
        sum_lo += __shfl_xor_sync(0xffffffffu, sum_lo, 1);
        sum_lo += __shfl_xor_sync(0xffffffffu, sum_lo, 2);
        sum_hi += __shfl_xor_sync(0xffffffffu, sum_hi, 1);
        sum_hi += __shfl_xor_sync(0xffffffffu, sum_hi, 2);
        l_lo = l_lo * alpha_lo + sum_lo;
        l_hi = l_hi * alpha_hi + sum_hi;

        #pragma unroll
        for (int n = 0; n < 8; n++) {
            O[n][0] *= alpha_lo; O[n][1] *= alpha_lo;
            O[n][2] *= alpha_hi; O[n][3] *= alpha_hi;
        }
        __syncwarp();

        // O += P @ V
        #pragma unroll
        for (int kk = 0; kk < 8; kk++) {
            uint32_t a[4];
            a[0] = __float_as_uint(Ps[(base_r + g    ) * PS_LD + kk * 8 + tg]);
            a[1] = __float_as_uint(Ps[(base_r + g + 8) * PS_LD + kk * 8 + tg]);
            a[2] = __float_as_uint(Ps[(base_r + g    ) * PS_LD + kk * 8 + tg + 4]);
            a[3] = __float_as_uint(Ps[(base_r + g + 8) * PS_LD + kk * 8 + tg + 4]);
            const float* vb = &Vs[(kk * 8 + tg) * VS_LD + g];
            #pragma unroll
            for (int n = 0; n < 8; n++) {
                uint32_t b0 = __float_as_uint(vb[n * 8]);
                uint32_t b1 = __float_as_uint(vb[n * 8 + 4 * VS_LD]);
                mma_tf32(O[n], a, b0, b1);
            }
        }
    }

    float inv_lo = 1.f / l_lo, inv_hi = 1.f / l_hi;
    size_t row_lo = ((size_t)batch * SEQ + qrow_lo) * DIM + head * HD;
    size_t row_hi = row_lo + (size_t)8 * DIM;
    #pragma unroll
    for (int n = 0; n < 8; n++) {
        *reinterpret_cast<float2*>(&g_ctx[row_lo + n * 8 + 2 * tg]) =
            make_float2(O[n][0] * inv_lo, O[n][1] * inv_lo);
        *reinterpret_cast<float2*>(&g_ctx[row_hi + n * 8 + 2 * tg]) =
            make_float2(O[n][2] * inv_hi, O[n][3] * inv_hi);
    }
}

// ---------------- launch ----------------------------------------------------
extern "C" void kernel_launch(void* const* d_in, const int* in_sizes, int n_in,
                              void* d_out, int out_size)
{
    const float* x         = (const float*)d_in[0];
    const float* w_q       = (const float*)d_in[1];
    const float* w_k       = (const float*)d_in[2];
    const float* w_v       = (const float*)d_in[3];
    const float* in_proj_w = (const float*)d_in[4];
    const float* in_proj_b = (const float*)d_in[5];
    const float* out_w     = (const float*)d_in[6];
    const float* out_b     = (const float*)d_in[7];
    float* out = (float*)d_out;

    setup_theta_kernel<<<1, 256>>>();
    setup_cs_kernel<<<SEQ, 256>>>();

    cudaFuncSetAttribute(gemm128<0>, cudaFuncAttributeMaxDynamicSharedMemorySize, GEMM_SMEM);
    cudaFuncSetAttribute(gemm128<1>, cudaFuncAttributeMaxDynamicSharedMemorySize, GEMM_SMEM);
    cudaFuncSetAttribute(gemm128<2>, cudaFuncAttributeMaxDynamicSharedMemorySize, GEMM_SMEM);

    // rot(x @ W^T) for q,k,v  (N = 1536)
    gemm128<0><<<dim3(12, 128), 256, GEMM_SMEM>>>(x, w_q, w_k, w_v, nullptr, nullptr);

    // in_proj + bias -> QKV [qkv][b][h][m][hd], Q pre-scaled, tf32-rounded
    gemm128<1><<<dim3(12, 128), 256, GEMM_SMEM>>>(nullptr, in_proj_w, nullptr, nullptr, in_proj_b, nullptr);

    // causal flash attention -> g_ctx [b][m][d]
    cudaFuncSetAttribute(flash2_kernel, cudaFuncAttributeMaxDynamicSharedMemorySize, FLASH_SMEM);
    flash2_kernel<<<dim3(64, 16), 256, FLASH_SMEM>>>();

    // out projection + bias -> d_out
    gemm128<2><<<dim3(4, 128), 256, GEMM_SMEM>>>(nullptr, out_w, nullptr, nullptr, out_b, out);
}

// round 7
// speedup vs baseline: 4.6063x; 1.6987x over previous
#include <cuda_runtime.h>
#include <cuda_fp16.h>
#include <math.h>
#include <stdint.h>

#define BATCH 8
#define SEQ   2048
#define DIM   512
#define NH    8
#define HD    64
#define BM    (BATCH*SEQ)   // 16384
#define HSZ   ((size_t)BATCH * NH * SEQ * HD)   // one q/k/v segment in halves

// ---------------- scratch (static device memory; no allocations allowed) ----
__device__ __align__(16) float  g_theta[256];
__device__ __align__(16) float  g_cs[SEQ][256][2];
__device__ __align__(16) __half g_x[(size_t)BM * DIM];
__device__ __align__(16) __half g_wq[DIM * DIM];
__device__ __align__(16) __half g_wk[DIM * DIM];
__device__ __align__(16) __half g_wv[DIM * DIM];
__device__ __align__(16) __half g_wip[3 * DIM * DIM];
__device__ __align__(16) __half g_wo[DIM * DIM];
__device__ __align__(16) __half g_YR[(size_t)BM * 1536];
__device__ __align__(16) __half g_QKV[3 * HSZ];   // Q,K: [b][h][pos][dd]; V: [b][h][dd][pos]
__device__ __align__(16) __half g_ctx[(size_t)BM * DIM];

__device__ __forceinline__ uint32_t smem_u32(const void* p) {
    uint32_t a;
    asm("{ .reg .u64 t; cvta.to.shared.u64 t, %1; cvt.u32.u64 %0, t; }" : "=r"(a) : "l"(p));
    return a;
}
__device__ __forceinline__ void cp16(uint32_t dst, const void* src) {
    asm volatile("cp.async.cg.shared.global [%0], [%1], 16;" :: "r"(dst), "l"(src));
}
__device__ __forceinline__ void mma_f16(float d[4], const uint32_t a[4],
                                        uint32_t b0, uint32_t b1) {
    asm volatile(
        "mma.sync.aligned.m16n8k16.row.col.f32.f16.f16.f32 "
        "{%0,%1,%2,%3}, {%4,%5,%6,%7}, {%8,%9}, {%0,%1,%2,%3};"
        : "+f"(d[0]), "+f"(d[1]), "+f"(d[2]), "+f"(d[3])
        : "r"(a[0]), "r"(a[1]), "r"(a[2]), "r"(a[3]), "r"(b0), "r"(b1));
}
__device__ __forceinline__ uint32_t h2u(float lo, float hi) {
    __half2 h = __floats2half2_rn(lo, hi);
    return *reinterpret_cast<uint32_t*>(&h);
}

// ---------------- setup ------------------------------------------------------
__global__ void setup_theta_kernel() {
    int i = threadIdx.x;
    double e = -2.0 * ((double)i - 1.0) / 512.0;
    g_theta[i] = (float)pow(10000.0, e);
}
__global__ void setup_cs_kernel() {
    int pos = blockIdx.x;
    int i = threadIdx.x;
    float ang = (float)pos * g_theta[i];
    float s, c;
    sincosf(ang, &s, &c);
    g_cs[pos][i][0] = c;
    g_cs[pos][i][1] = s;
}
__global__ void f2h_kernel(const float4* __restrict__ src,
                           __half2* __restrict__ dst, int n4) {
    int i = blockIdx.x * 256 + threadIdx.x;
    if (i < n4) {
        float4 v = src[i];
        dst[2 * i]     = __floats2half2_rn(v.x, v.y);
        dst[2 * i + 1] = __floats2half2_rn(v.z, v.w);
    }
}

// ---------------- 128x128-tile FP16 GEMM, 128 threads, cp.async 2-stage ------
// MODE 0: YR = rope(g_x @ {wq,wk,wv}^T)         -> half
// MODE 1: QKV = g_YR @ wip^T + b                -> half, scatter, Q scale, V transposed
// MODE 2: out = g_ctx @ wo^T + out_b            -> fp32
#define PH 40                          // pitch in halves (128 rows x 40)
#define STAGE_H (128 * PH)             // halves per matrix per stage (5120)
#define GEMM_SMEM (2 * 2 * STAGE_H * 2) // 40960 bytes

template<int MODE>
__global__ __launch_bounds__(128) void gemm128h(
    const float* __restrict__ bias, float* __restrict__ Cout)
{
    extern __shared__ __half hsm[];

    const int m0  = blockIdx.y * 128;
    const int n0g = blockIdx.x * 128;
    const int seg = n0g >> 9;
    const int n0  = n0g & 511;

    const __half* Ap;
    const __half* Bp;
    int lda;
    if (MODE == 0) {
        const __half* Bsel = (seg == 0) ? g_wq : ((seg == 1) ? g_wk : g_wv);
        Bp = Bsel + (size_t)n0 * DIM;
        Ap = g_x + (size_t)m0 * DIM;  lda = DIM;
    } else if (MODE == 1) {
        Bp = g_wip + (size_t)n0g * DIM;
        Ap = g_YR + (size_t)m0 * 1536 + seg * DIM;  lda = 1536;
    } else {
        Bp = g_wo + (size_t)n0g * DIM;
        Ap = g_ctx + (size_t)m0 * DIM;  lda = DIM;
    }

    const int t    = threadIdx.x;
    const int warp = t >> 5, lane = t & 31;
    const int wr   = warp >> 1, wc = warp & 1;      // 2x2 warps, 64x64 each
    const int g    = lane >> 2, tg = lane & 3;

    const uint32_t sbase = smem_u32(hsm);
    const int ld_row = t >> 2;          // 0..31
    const int ld_c16 = t & 3;           // 16B unit within 64B row

    float acc[4][8][4];
    #pragma unroll
    for (int mi = 0; mi < 4; mi++)
        #pragma unroll
        for (int ni = 0; ni < 8; ni++)
            #pragma unroll
            for (int r = 0; r < 4; r++) acc[mi][ni][r] = 0.f;

    // k-chunk = 32 halves (64B = 4x16B per row); 128 rows; 128 threads -> 4 iters
    auto issue_tile = [&](int buf, int k0) {
        uint32_t abase = sbase + (uint32_t)buf * 2 * STAGE_H * 2;
        uint32_t bbase = abase + STAGE_H * 2;
        #pragma unroll
        for (int it = 0; it < 4; it++) {
            int row = ld_row + it * 32;
            cp16(abase + (uint32_t)(row * (PH * 2) + ld_c16 * 16),
                 Ap + (size_t)row * lda + k0 + ld_c16 * 8);
            cp16(bbase + (uint32_t)(row * (PH * 2) + ld_c16 * 16),
                 Bp + (size_t)row * DIM + k0 + ld_c16 * 8);
        }
        asm volatile("cp.async.commit_group;");
    };

    issue_tile(0, 0);

    #pragma unroll 1
    for (int kt = 0; kt < 16; kt++) {
        asm volatile("cp.async.wait_group 0;");
        __syncthreads();
        if (kt < 15) issue_tile((kt + 1) & 1, (kt + 1) * 32);

        const __half* As = hsm + (kt & 1) * 2 * STAGE_H;
        const __half* Bs = As + STAGE_H;
        const __half* Abase = As + (wr * 64 + g) * PH + 2 * tg;
        const __half* Bbase = Bs + (wc * 64 + g) * PH + 2 * tg;

        #pragma unroll
        for (int kb = 0; kb < 2; kb++) {
            const int kof = kb * 16;
            uint32_t a[4][4];
            #pragma unroll
            for (int mi = 0; mi < 4; mi++) {
                const __half* ap = Abase + mi * 16 * PH + kof;
                a[mi][0] = *reinterpret_cast<const uint32_t*>(ap);
                a[mi][1] = *reinterpret_cast<const uint32_t*>(ap + 8 * PH);
                a[mi][2] = *reinterpret_cast<const uint32_t*>(ap + 8);
                a[mi][3] = *reinterpret_cast<const uint32_t*>(ap + 8 * PH + 8);
            }
            uint32_t b[8][2];
            #pragma unroll
            for (int ni = 0; ni < 8; ni++) {
                const __half* bp = Bbase + ni * 8 * PH + kof;
                b[ni][0] = *reinterpret_cast<const uint32_t*>(bp);
                b[ni][1] = *reinterpret_cast<const uint32_t*>(bp + 8);
            }
            #pragma unroll
            for (int mi = 0; mi < 4; mi++)
                #pragma unroll
                for (int ni = 0; ni < 8; ni++)
                    mma_f16(acc[mi][ni], a[mi], b[ni][0], b[ni][1]);
        }
        __syncthreads();
    }

    // ---- fused epilogue ----
    const int gm_base = m0 + wr * 64;
    const int gn_base = n0g + wc * 64;

    #pragma unroll
    for (int mi = 0; mi < 4; mi++) {
        #pragma unroll
        for (int h = 0; h < 2; h++) {
            const int gm  = gm_base + mi * 16 + g + h * 8;
            const int pos = gm & (SEQ - 1);
            #pragma unroll
            for (int ni = 0; ni < 8; ni++) {
                float c0 = acc[mi][ni][2 * h];
                float c1 = acc[mi][ni][2 * h + 1];
                const int col = gn_base + ni * 8 + 2 * tg;
                if (MODE == 0) {
                    const int tp = (col & 511) >> 1;
                    float2 cs = *reinterpret_cast<const float2*>(&g_cs[pos][tp][0]);
                    float r0 =  c0 * cs.x + c1 * cs.y;
                    float r1 = -c0 * cs.y + c1 * cs.x;
                    *reinterpret_cast<uint32_t*>(&g_YR[(size_t)gm * 1536 + col]) = h2u(r0, r1);
                } else if (MODE == 1) {
                    float2 bb = *reinterpret_cast<const float2*>(&bias[col]);
                    float v0 = c0 + bb.x, v1 = c1 + bb.y;
                    if (seg == 0) { v0 *= 0.125f; v1 *= 0.125f; }
                    const int batch = gm >> 11;
                    const int head  = (col & 511) >> 6;
                    const int dd    = col & 63;
                    if (seg < 2) {
                        size_t o = (size_t)seg * HSZ
                                 + ((size_t)(batch * NH + head) * SEQ + pos) * HD + dd;
                        *reinterpret_cast<uint32_t*>(&g_QKV[o]) = h2u(v0, v1);
                    } else {
                        size_t o = 2 * HSZ + ((size_t)(batch * NH + head) * HD + dd) * SEQ + pos;
                        g_QKV[o]       = __float2half_rn(v0);
                        g_QKV[o + SEQ] = __float2half_rn(v1);
                    }
                } else {
                    float2 bb = *reinterpret_cast<const float2*>(&bias[col]);
                    *reinterpret_cast<float2*>(&Cout[(size_t)gm * DIM + col]) =
                        make_float2(c0 + bb.x, c1 + bb.y);
                }
            }
        }
    }
}

// ---------------- flash attention fp16: P stays in registers -----------------
#define FP 72                              // flash smem pitch in halves
#define FLASH_SMEM (2 * 2 * 64 * FP * 2)   // K + V double-buffered = 36864 B

__global__ void __launch_bounds__(256, 2) flash3_kernel()
{
    extern __shared__ __half fsm[];
    __half* Ksb = fsm;                     // [2][64][FP]
    __half* Vsb = fsm + 2 * 64 * FP;       // [2][64][FP]  (V^T: rows=hd, cols=pos)

    const int bh = blockIdx.x;
    const int qt = 15 - blockIdx.y;        // heavy tiles first
    const int batch = bh >> 3, head = bh & 7;

    const int t = threadIdx.x;
    const int warp = t >> 5, lane = t & 31;
    const int g = lane >> 2, tg = lane & 3;
    const int base_r = warp * 16;
    const int qrow_lo = qt * 128 + base_r + g;
    const int qrow_hi = qrow_lo + 8;

    const __half* Qg = g_QKV + ((size_t)(batch * NH + head)) * SEQ * HD;
    const __half* Kg = g_QKV + HSZ + ((size_t)(batch * NH + head)) * SEQ * HD;
    const __half* Vg = g_QKV + 2 * HSZ + ((size_t)(batch * NH + head)) * HD * SEQ;

    const uint32_t ksb = smem_u32(Ksb);
    const uint32_t vsb = smem_u32(Vsb);

    // K tile: 64 keys x 64 hd (row=key). V tile: 64 hd x 64 pos (row=hd).
    auto issue_kv = [&](int kt) {
        int buf = kt & 1;
        #pragma unroll
        for (int it = 0; it < 2; it++) {
            int u = t + it * 256;          // 0..511 16B units
            int r = u >> 3, c = u & 7;
            cp16(ksb + (uint32_t)(buf * 64 * FP * 2 + r * FP * 2 + c * 16),
                 Kg + (size_t)kt * 64 * HD + (size_t)r * HD + c * 8);
            cp16(vsb + (uint32_t)(buf * 64 * FP * 2 + r * FP * 2 + c * 16),
                 Vg + (size_t)r * SEQ + kt * 64 + c * 8);
        }
        asm volatile("cp.async.commit_group;");
    };

    const int nkt = 2 * (qt + 1);
    issue_kv(0);

    // Q a-fragments (halves), registers for whole loop
    uint32_t Qa[4][4];
    #pragma unroll
    for (int kb = 0; kb < 4; kb++) {
        int c0 = kb * 16 + 2 * tg;
        Qa[kb][0] = *reinterpret_cast<const uint32_t*>(Qg + (size_t)qrow_lo * HD + c0);
        Qa[kb][1] = *reinterpret_cast<const uint32_t*>(Qg + (size_t)qrow_hi * HD + c0);
        Qa[kb][2] = *reinterpret_cast<const uint32_t*>(Qg + (size_t)qrow_lo * HD + c0 + 8);
        Qa[kb][3] = *reinterpret_cast<const uint32_t*>(Qg + (size_t)qrow_hi * HD + c0 + 8);
    }

    float O[8][4];
    #pragma unroll
    for (int n = 0; n < 8; n++) { O[n][0] = O[n][1] = O[n][2] = O[n][3] = 0.f; }
    float m_lo = -INFINITY, m_hi = -INFINITY, l_lo = 0.f, l_hi = 0.f;

    #pragma unroll 1
    for (int kt = 0; kt < nkt; kt++) {
        asm volatile("cp.async.wait_group 0;");
        __syncthreads();
        if (kt + 1 < nkt) issue_kv(kt + 1);

        const __half* Ks = Ksb + (kt & 1) * 64 * FP;
        const __half* Vs = Vsb + (kt & 1) * 64 * FP;

        // S = Q @ K^T
        float s[8][4];
        #pragma unroll
        for (int n = 0; n < 8; n++) { s[n][0] = s[n][1] = s[n][2] = s[n][3] = 0.f; }
        #pragma unroll
        for (int n = 0; n < 8; n++) {
            const __half* kb8 = Ks + (n * 8 + g) * FP + 2 * tg;
            #pragma unroll
            for (int kb = 0; kb < 4; kb++) {
                uint32_t b0 = *reinterpret_cast<const uint32_t*>(kb8 + kb * 16);
                uint32_t b1 = *reinterpret_cast<const uint32_t*>(kb8 + kb * 16 + 8);
                mma_f16(s[n], Qa[kb], b0, b1);
            }
        }

        // causal mask near diagonal
        if (kt * 64 + 63 > qt * 128 + base_r) {
            #pragma unroll
            for (int n = 0; n < 8; n++) {
                int gc0 = kt * 64 + n * 8 + 2 * tg;
                int gc1 = gc0 + 1;
                if (gc0 > qrow_lo) s[n][0] = -1e30f;
                if (gc1 > qrow_lo) s[n][1] = -1e30f;
                if (gc0 > qrow_hi) s[n][2] = -1e30f;
                if (gc1 > qrow_hi) s[n][3] = -1e30f;
            }
        }

        // online softmax (fp32)
        float mx_lo = -1e30f, mx_hi = -1e30f;
        #pragma unroll
        for (int n = 0; n < 8; n++) {
            mx_lo = fmaxf(mx_lo, fmaxf(s[n][0], s[n][1]));
            mx_hi = fmaxf(mx_hi, fmaxf(s[n][2], s[n][3]));
        }
        mx_lo = fmaxf(mx_lo, __shfl_xor_sync(0xffffffffu, mx_lo, 1));
        mx_lo = fmaxf(mx_lo, __shfl_xor_sync(0xffffffffu, mx_lo, 2));
        mx_hi = fmaxf(mx_hi, __shfl_xor_sync(0xffffffffu, mx_hi, 1));
        mx_hi = fmaxf(mx_hi, __shfl_xor_sync(0xffffffffu, mx_hi, 2));

        float mnew_lo = fmaxf(m_lo, mx_lo);
        float mnew_hi = fmaxf(m_hi, mx_hi);
        float alpha_lo = __expf(m_lo - mnew_lo);
        float alpha_hi = __expf(m_hi - mnew_hi);
        m_lo = mnew_lo; m_hi = mnew_hi;

        float p[8][4];
        float sum_lo = 0.f, sum_hi = 0.f;
        #pragma unroll
        for (int n = 0; n < 8; n++) {
            p[n][0] = __expf(s[n][0] - mnew_lo);
            p[n][1] = __expf(s[n][1] - mnew_lo);
            p[n][2] = __expf(s[n][2] - mnew_hi);
            p[n][3] = __expf(s[n][3] - mnew_hi);
            sum_lo += p[n][0] + p[n][1];
            sum_hi += p[n][2] + p[n][3];
        }
        sum_lo += __shfl_xor_sync(0xffffffffu, sum_lo, 1);
        sum_lo += __shfl_xor_sync(0xffffffffu, sum_lo, 2);
        sum_hi += __shfl_xor_sync(0xffffffffu, sum_hi, 1);
        sum_hi += __shfl_xor_sync(0xffffffffu, sum_hi, 2);
        l_lo = l_lo * alpha_lo + sum_lo;
        l_hi = l_hi * alpha_hi + sum_hi;

        // P a-fragments directly from registers (no smem round-trip)
        uint32_t Pa[4][4];
        #pragma unroll
        for (int kb = 0; kb < 4; kb++) {
            Pa[kb][0] = h2u(p[2 * kb][0],     p[2 * kb][1]);
            Pa[kb][1] = h2u(p[2 * kb][2],     p[2 * kb][3]);
            Pa[kb][2] = h2u(p[2 * kb + 1][0], p[2 * kb + 1][1]);
            Pa[kb][3] = h2u(p[2 * kb + 1][2], p[2 * kb + 1][3]);
        }

        #pragma unroll
        for (int n = 0; n < 8; n++) {
            O[n][0] *= alpha_lo; O[n][1] *= alpha_lo;
            O[n][2] *= alpha_hi; O[n][3] *= alpha_hi;
        }

        // O += P @ V   (B = V^T in smem: rows=hd, cols=key)
        #pragma unroll
        for (int kb = 0; kb < 4; kb++) {
            #pragma unroll
            for (int n = 0; n < 8; n++) {
                const __half* vb = Vs + (n * 8 + g) * FP + kb * 16 + 2 * tg;
                uint32_t b0 = *reinterpret_cast<const uint32_t*>(vb);
                uint32_t b1 = *reinterpret_cast<const uint32_t*>(vb + 8);
                mma_f16(O[n], Pa[kb], b0, b1);
            }
        }
    }

    // epilogue: normalize, write half to g_ctx
    float inv_lo = 1.f / l_lo, inv_hi = 1.f / l_hi;
    size_t row_lo = ((size_t)batch * SEQ + qrow_lo) * DIM + head * HD;
    size_t row_hi = row_lo + (size_t)8 * DIM;
    #pragma unroll
    for (int n = 0; n < 8; n++) {
        int col = n * 8 + 2 * tg;
        *reinterpret_cast<uint32_t*>(&g_ctx[row_lo + col]) =
            h2u(O[n][0] * inv_lo, O[n][1] * inv_lo);
        *reinterpret_cast<uint32_t*>(&g_ctx[row_hi + col]) =
            h2u(O[n][2] * inv_hi, O[n][3] * inv_hi);
    }
}

// ---------------- launch ----------------------------------------------------
extern "C" void kernel_launch(void* const* d_in, const int* in_sizes, int n_in,
                              void* d_out, int out_size)
{
    const float* x         = (const float*)d_in[0];
    const float* w_q       = (const float*)d_in[1];
    const float* w_k       = (const float*)d_in[2];
    const float* w_v       = (const float*)d_in[3];
    const float* in_proj_w = (const float*)d_in[4];
    const float* in_proj_b = (const float*)d_in[5];
    const float* out_w     = (const float*)d_in[6];
    const float* out_b     = (const float*)d_in[7];
    float* out = (float*)d_out;

    void *p_x, *p_wq, *p_wk, *p_wv, *p_wip, *p_wo;
    cudaGetSymbolAddress(&p_x,   g_x);
    cudaGetSymbolAddress(&p_wq,  g_wq);
    cudaGetSymbolAddress(&p_wk,  g_wk);
    cudaGetSymbolAddress(&p_wv,  g_wv);
    cudaGetSymbolAddress(&p_wip, g_wip);
    cudaGetSymbolAddress(&p_wo,  g_wo);

    setup_theta_kernel<<<1, 256>>>();
    setup_cs_kernel<<<SEQ, 256>>>();

    f2h_kernel<<<(BM * DIM / 4 + 255) / 256, 256>>>((const float4*)x, (__half2*)p_x, BM * DIM / 4);
    f2h_kernel<<<(DIM * DIM / 4 + 255) / 256, 256>>>((const float4*)w_q, (__half2*)p_wq, DIM * DIM / 4);
    f2h_kernel<<<(DIM * DIM / 4 + 255) / 256, 256>>>((const float4*)w_k, (__half2*)p_wk, DIM * DIM / 4);
    f2h_kernel<<<(DIM * DIM / 4 + 255) / 256, 256>>>((const float4*)w_v, (__half2*)p_wv, DIM * DIM / 4);
    f2h_kernel<<<(3 * DIM * DIM / 4 + 255) / 256, 256>>>((const float4*)in_proj_w, (__half2*)p_wip, 3 * DIM * DIM / 4);
    f2h_kernel<<<(DIM * DIM / 4 + 255) / 256, 256>>>((const float4*)out_w, (__half2*)p_wo, DIM * DIM / 4);

    cudaFuncSetAttribute(gemm128h<0>, cudaFuncAttributeMaxDynamicSharedMemorySize, GEMM_SMEM);
    cudaFuncSetAttribute(gemm128h<1>, cudaFuncAttributeMaxDynamicSharedMemorySize, GEMM_SMEM);
    cudaFuncSetAttribute(gemm128h<2>, cudaFuncAttributeMaxDynamicSharedMemorySize, GEMM_SMEM);
    cudaFuncSetAttribute(flash3_kernel, cudaFuncAttributeMaxDynamicSharedMemorySize, FLASH_SMEM);

    // rot(x @ W^T) for q,k,v  (N = 1536)
    gemm128h<0><<<dim3(12, 128), 128, GEMM_SMEM>>>(nullptr, nullptr);
    // in_proj + bias -> QKV (scatter, Q scaled, V transposed)
    gemm128h<1><<<dim3(12, 128), 128, GEMM_SMEM>>>(in_proj_b, nullptr);
    // causal flash attention -> g_ctx
    flash3_kernel<<<dim3(64, 16), 256, FLASH_SMEM>>>();
    // out projection + bias -> d_out (fp32)
    gemm128h<2><<<dim3(4, 128), 128, GEMM_SMEM>>>(out_b, out);
}

// round 8
// speedup vs baseline: 4.6789x; 1.0158x over previous
#include <cuda_runtime.h>
#include <cuda_fp16.h>
#include <math.h>
#include <stdint.h>

#define BATCH 8
#define SEQ   2048
#define DIM   512
#define NH    8
#define HD    64
#define BM    (BATCH*SEQ)   // 16384
#define HSZ   ((size_t)BATCH * NH * SEQ * HD)   // one q/k/v segment in halves

// ---------------- scratch (static device memory; no allocations allowed) ----
__device__ __align__(16) float  g_theta[256];
__device__ __align__(16) float  g_cs[SEQ][256][2];
__device__ __align__(16) __half g_x[(size_t)BM * DIM];
__device__ __align__(16) __half g_wq[DIM * DIM];
__device__ __align__(16) __half g_wk[DIM * DIM];
__device__ __align__(16) __half g_wv[DIM * DIM];
__device__ __align__(16) __half g_wip[3 * DIM * DIM];
__device__ __align__(16) __half g_wo[DIM * DIM];
__device__ __align__(16) __half g_YR[(size_t)BM * 1536];
__device__ __align__(16) __half g_QKV[3 * HSZ];   // Q,K: [b][h][pos][dd]; V: [b][h][dd][pos]
__device__ __align__(16) __half g_ctx[(size_t)BM * DIM];

__device__ __forceinline__ uint32_t smem_u32(const void* p) {
    uint32_t a;
    asm("{ .reg .u64 t; cvta.to.shared.u64 t, %1; cvt.u32.u64 %0, t; }" : "=r"(a) : "l"(p));
    return a;
}
__device__ __forceinline__ void cp16(uint32_t dst, const void* src) {
    asm volatile("cp.async.cg.shared.global [%0], [%1], 16;" :: "r"(dst), "l"(src));
}
__device__ __forceinline__ void mma_f16(float d[4], const uint32_t a[4],
                                        uint32_t b0, uint32_t b1) {
    asm volatile(
        "mma.sync.aligned.m16n8k16.row.col.f32.f16.f16.f32 "
        "{%0,%1,%2,%3}, {%4,%5,%6,%7}, {%8,%9}, {%0,%1,%2,%3};"
        : "+f"(d[0]), "+f"(d[1]), "+f"(d[2]), "+f"(d[3])
        : "r"(a[0]), "r"(a[1]), "r"(a[2]), "r"(a[3]), "r"(b0), "r"(b1));
}
__device__ __forceinline__ uint32_t h2u(float lo, float hi) {
    __half2 h = __floats2half2_rn(lo, hi);
    return *reinterpret_cast<uint32_t*>(&h);
}

// ---------------- setup ------------------------------------------------------
__global__ void setup_theta_kernel() {
    int i = threadIdx.x;
    double e = -2.0 * ((double)i - 1.0) / 512.0;
    g_theta[i] = (float)pow(10000.0, e);
}
__global__ void setup_cs_kernel() {
    int pos = blockIdx.x;
    int i = threadIdx.x;
    float ang = (float)pos * g_theta[i];
    float s, c;
    sincosf(ang, &s, &c);
    g_cs[pos][i][0] = c;
    g_cs[pos][i][1] = s;
}

// one launch converts all fp32 inputs to fp16 scratch
struct F2HJobs {
    const float4* src[6];
    __half2*      dst[6];
    int           n4[6];
};
__global__ void f2h_all_kernel(F2HJobs jobs) {
    const int stride = gridDim.x * blockDim.x;
    #pragma unroll
    for (int s = 0; s < 6; s++) {
        const float4* src = jobs.src[s];
        __half2* dst = jobs.dst[s];
        const int n4 = jobs.n4[s];
        for (int i = blockIdx.x * blockDim.x + threadIdx.x; i < n4; i += stride) {
            float4 v = src[i];
            dst[2 * i]     = __floats2half2_rn(v.x, v.y);
            dst[2 * i + 1] = __floats2half2_rn(v.z, v.w);
        }
    }
}

// ---------------- 128x128-tile FP16 GEMM, 128 threads, cp.async 3-stage ------
// MODE 0: YR = rope(g_x @ {wq,wk,wv}^T)         -> half
// MODE 1: QKV = g_YR @ wip^T + b                -> half, scatter, Q scale, V transposed
// MODE 2: out = g_ctx @ wo^T + out_b            -> fp32
#define PH 40                          // pitch in halves (128 rows x 40)
#define STAGE_H (128 * PH)             // halves per matrix per stage (5120)
#define NSTAGE 3
#define GEMM_SMEM (NSTAGE * 2 * STAGE_H * 2)   // 61440 bytes

template<int MODE>
__global__ __launch_bounds__(128) void gemm128h(
    const float* __restrict__ bias, float* __restrict__ Cout)
{
    extern __shared__ __half hsm[];

    const int m0  = blockIdx.y * 128;
    const int n0g = blockIdx.x * 128;
    const int seg = n0g >> 9;
    const int n0  = n0g & 511;

    const __half* Ap;
    const __half* Bp;
    int lda;
    if (MODE == 0) {
        const __half* Bsel = (seg == 0) ? g_wq : ((seg == 1) ? g_wk : g_wv);
        Bp = Bsel + (size_t)n0 * DIM;
        Ap = g_x + (size_t)m0 * DIM;  lda = DIM;
    } else if (MODE == 1) {
        Bp = g_wip + (size_t)n0g * DIM;
        Ap = g_YR + (size_t)m0 * 1536 + seg * DIM;  lda = 1536;
    } else {
        Bp = g_wo + (size_t)n0g * DIM;
        Ap = g_ctx + (size_t)m0 * DIM;  lda = DIM;
    }

    const int t    = threadIdx.x;
    const int warp = t >> 5, lane = t & 31;
    const int wr   = warp >> 1, wc = warp & 1;      // 2x2 warps, 64x64 each
    const int g    = lane >> 2, tg = lane & 3;

    const uint32_t sbase = smem_u32(hsm);
    const int ld_row = t >> 2;          // 0..31
    const int ld_c16 = t & 3;           // 16B unit within 64B row

    float acc[4][8][4];
    #pragma unroll
    for (int mi = 0; mi < 4; mi++)
        #pragma unroll
        for (int ni = 0; ni < 8; ni++)
            #pragma unroll
            for (int r = 0; r < 4; r++) acc[mi][ni][r] = 0.f;

    // k-chunk = 32 halves (64B = 4x16B per row); 128 rows; 128 threads -> 4 iters
    auto issue_tile = [&](int slot, int k0) {
        uint32_t abase = sbase + (uint32_t)slot * 2 * STAGE_H * 2;
        uint32_t bbase = abase + STAGE_H * 2;
        #pragma unroll
        for (int it = 0; it < 4; it++) {
            int row = ld_row + it * 32;
            cp16(abase + (uint32_t)(row * (PH * 2) + ld_c16 * 16),
                 Ap + (size_t)row * lda + k0 + ld_c16 * 8);
            cp16(bbase + (uint32_t)(row * (PH * 2) + ld_c16 * 16),
                 Bp + (size_t)row * DIM + k0 + ld_c16 * 8);
        }
        asm volatile("cp.async.commit_group;");
    };

    issue_tile(0, 0);
    issue_tile(1, 32);

    #pragma unroll 1
    for (int kt = 0; kt < 16; kt++) {
        if (kt < 15) {
            asm volatile("cp.async.wait_group 1;");
        } else {
            asm volatile("cp.async.wait_group 0;");
        }
        __syncthreads();
        if (kt + 2 < 16) issue_tile((kt + 2) % NSTAGE, (kt + 2) * 32);

        const __half* As = hsm + (kt % NSTAGE) * 2 * STAGE_H;
        const __half* Bs = As + STAGE_H;
        const __half* Abase = As + (wr * 64 + g) * PH + 2 * tg;
        const __half* Bbase = Bs + (wc * 64 + g) * PH + 2 * tg;

        #pragma unroll
        for (int kb = 0; kb < 2; kb++) {
            const int kof = kb * 16;
            uint32_t a[4][4];
            #pragma unroll
            for (int mi = 0; mi < 4; mi++) {
                const __half* ap = Abase + mi * 16 * PH + kof;
                a[mi][0] = *reinterpret_cast<const uint32_t*>(ap);
                a[mi][1] = *reinterpret_cast<const uint32_t*>(ap + 8 * PH);
                a[mi][2] = *reinterpret_cast<const uint32_t*>(ap + 8);
                a[mi][3] = *reinterpret_cast<const uint32_t*>(ap + 8 * PH + 8);
            }
            uint32_t b[8][2];
            #pragma unroll
            for (int ni = 0; ni < 8; ni++) {
                const __half* bp = Bbase + ni * 8 * PH + kof;
                b[ni][0] = *reinterpret_cast<const uint32_t*>(bp);
                b[ni][1] = *reinterpret_cast<const uint32_t*>(bp + 8);
            }
            #pragma unroll
            for (int mi = 0; mi < 4; mi++)
                #pragma unroll
                for (int ni = 0; ni < 8; ni++)
                    mma_f16(acc[mi][ni], a[mi], b[ni][0], b[ni][1]);
        }
        __syncthreads();
    }

    // ---- fused epilogue ----
    const int gm_base = m0 + wr * 64;
    const int gn_base = n0g + wc * 64;

    #pragma unroll
    for (int mi = 0; mi < 4; mi++) {
        #pragma unroll
        for (int h = 0; h < 2; h++) {
            const int gm  = gm_base + mi * 16 + g + h * 8;
            const int pos = gm & (SEQ - 1);
            #pragma unroll
            for (int ni = 0; ni < 8; ni++) {
                float c0 = acc[mi][ni][2 * h];
                float c1 = acc[mi][ni][2 * h + 1];
                const int col = gn_base + ni * 8 + 2 * tg;
                if (MODE == 0) {
                    const int tp = (col & 511) >> 1;
                    float2 cs = *reinterpret_cast<const float2*>(&g_cs[pos][tp][0]);
                    float r0 =  c0 * cs.x + c1 * cs.y;
                    float r1 = -c0 * cs.y + c1 * cs.x;
                    *reinterpret_cast<uint32_t*>(&g_YR[(size_t)gm * 1536 + col]) = h2u(r0, r1);
                } else if (MODE == 1) {
                    float2 bb = *reinterpret_cast<const float2*>(&bias[col]);
                    float v0 = c0 + bb.x, v1 = c1 + bb.y;
                    if (seg == 0) { v0 *= 0.125f; v1 *= 0.125f; }
                    const int batch = gm >> 11;
                    const int head  = (col & 511) >> 6;
                    const int dd    = col & 63;
                    if (seg < 2) {
                        size_t o = (size_t)seg * HSZ
                                 + ((size_t)(batch * NH + head) * SEQ + pos) * HD + dd;
                        *reinterpret_cast<uint32_t*>(&g_QKV[o]) = h2u(v0, v1);
                    } else {
                        size_t o = 2 * HSZ + ((size_t)(batch * NH + head) * HD + dd) * SEQ + pos;
                        g_QKV[o]       = __float2half_rn(v0);
                        g_QKV[o + SEQ] = __float2half_rn(v1);
                    }
                } else {
                    float2 bb = *reinterpret_cast<const float2*>(&bias[col]);
                    *reinterpret_cast<float2*>(&Cout[(size_t)gm * DIM + col]) =
                        make_float2(c0 + bb.x, c1 + bb.y);
                }
            }
        }
    }
}

// ---------------- flash attention fp16: P stays in registers -----------------
#define FP 72                              // flash smem pitch in halves
#define FLASH_SMEM (2 * 2 * 64 * FP * 2)   // K + V double-buffered = 36864 B

__global__ void __launch_bounds__(256, 2) flash3_kernel()
{
    extern __shared__ __half fsm[];
    __half* Ksb = fsm;                     // [2][64][FP]
    __half* Vsb = fsm + 2 * 64 * FP;       // [2][64][FP]  (V^T: rows=hd, cols=pos)

    const int bh = blockIdx.x;
    const int qt = 15 - blockIdx.y;        // heavy tiles first
    const int batch = bh >> 3, head = bh & 7;

    const int t = threadIdx.x;
    const int warp = t >> 5, lane = t & 31;
    const int g = lane >> 2, tg = lane & 3;
    const int base_r = warp * 16;
    const int qrow_lo = qt * 128 + base_r + g;
    const int qrow_hi = qrow_lo + 8;

    const __half* Qg = g_QKV + ((size_t)(batch * NH + head)) * SEQ * HD;
    const __half* Kg = g_QKV + HSZ + ((size_t)(batch * NH + head)) * SEQ * HD;
    const __half* Vg = g_QKV + 2 * HSZ + ((size_t)(batch * NH + head)) * HD * SEQ;

    const uint32_t ksb = smem_u32(Ksb);
    const uint32_t vsb = smem_u32(Vsb);

    // K tile: 64 keys x 64 hd (row=key). V tile: 64 hd x 64 pos (row=hd).
    auto issue_kv = [&](int kt) {
        int buf = kt & 1;
        #pragma unroll
        for (int it = 0; it < 2; it++) {
            int u = t + it * 256;          // 0..511 16B units
            int r = u >> 3, c = u & 7;
            cp16(ksb + (uint32_t)(buf * 64 * FP * 2 + r * FP * 2 + c * 16),
                 Kg + (size_t)kt * 64 * HD + (size_t)r * HD + c * 8);
            cp16(vsb + (uint32_t)(buf * 64 * FP * 2 + r * FP * 2 + c * 16),
                 Vg + (size_t)r * SEQ + kt * 64 + c * 8);
        }
        asm volatile("cp.async.commit_group;");
    };

    const int nkt = 2 * (qt + 1);
    issue_kv(0);

    // Q a-fragments (halves), registers for whole loop
    uint32_t Qa[4][4];
    #pragma unroll
    for (int kb = 0; kb < 4; kb++) {
        int c0 = kb * 16 + 2 * tg;
        Qa[kb][0] = *reinterpret_cast<const uint32_t*>(Qg + (size_t)qrow_lo * HD + c0);
        Qa[kb][1] = *reinterpret_cast<const uint32_t*>(Qg + (size_t)qrow_hi * HD + c0);
        Qa[kb][2] = *reinterpret_cast<const uint32_t*>(Qg + (size_t)qrow_lo * HD + c0 + 8);
        Qa[kb][3] = *reinterpret_cast<const uint32_t*>(Qg + (size_t)qrow_hi * HD + c0 + 8);
    }

    float O[8][4];
    #pragma unroll
    for (int n = 0; n < 8; n++) { O[n][0] = O[n][1] = O[n][2] = O[n][3] = 0.f; }
    float m_lo = -INFINITY, m_hi = -INFINITY, l_lo = 0.f, l_hi = 0.f;

    #pragma unroll 1
    for (int kt = 0; kt < nkt; kt++) {
        asm volatile("cp.async.wait_group 0;");
        __syncthreads();
        if (kt + 1 < nkt) issue_kv(kt + 1);

        const __half* Ks = Ksb + (kt & 1) * 64 * FP;
        const __half* Vs = Vsb + (kt & 1) * 64 * FP;

        // S = Q @ K^T
        float s[8][4];
        #pragma unroll
        for (int n = 0; n < 8; n++) { s[n][0] = s[n][1] = s[n][2] = s[n][3] = 0.f; }
        #pragma unroll
        for (int n = 0; n < 8; n++) {
            const __half* kb8 = Ks + (n * 8 + g) * FP + 2 * tg;
            #pragma unroll
            for (int kb = 0; kb < 4; kb++) {
                uint32_t b0 = *reinterpret_cast<const uint32_t*>(kb8 + kb * 16);
                uint32_t b1 = *reinterpret_cast<const uint32_t*>(kb8 + kb * 16 + 8);
                mma_f16(s[n], Qa[kb], b0, b1);
            }
        }

        // causal mask near diagonal
        if (kt * 64 + 63 > qt * 128 + base_r) {
            #pragma unroll
            for (int n = 0; n < 8; n++) {
                int gc0 = kt * 64 + n * 8 + 2 * tg;
                int gc1 = gc0 + 1;
                if (gc0 > qrow_lo) s[n][0] = -1e30f;
                if (gc1 > qrow_lo) s[n][1] = -1e30f;
                if (gc0 > qrow_hi) s[n][2] = -1e30f;
                if (gc1 > qrow_hi) s[n][3] = -1e30f;
            }
        }

        // online softmax (fp32)
        float mx_lo = -1e30f, mx_hi = -1e30f;
        #pragma unroll
        for (int n = 0; n < 8; n++) {
            mx_lo = fmaxf(mx_lo, fmaxf(s[n][0], s[n][1]));
            mx_hi = fmaxf(mx_hi, fmaxf(s[n][2], s[n][3]));
        }
        mx_lo = fmaxf(mx_lo, __shfl_xor_sync(0xffffffffu, mx_lo, 1));
        mx_lo = fmaxf(mx_lo, __shfl_xor_sync(0xffffffffu, mx_lo, 2));
        mx_hi = fmaxf(mx_hi, __shfl_xor_sync(0xffffffffu, mx_hi, 1));
        mx_hi = fmaxf(mx_hi, __shfl_xor_sync(0xffffffffu, mx_hi, 2));

        float mnew_lo = fmaxf(m_lo, mx_lo);
        float mnew_hi = fmaxf(m_hi, mx_hi);
        float alpha_lo = __expf(m_lo - mnew_lo);
        float alpha_hi = __expf(m_hi - mnew_hi);
        m_lo = mnew_lo; m_hi = mnew_hi;

        float p[8][4];
        float sum_lo = 0.f, sum_hi = 0.f;
        #pragma unroll
        for (int n = 0; n < 8; n++) {
            p[n][0] = __expf(s[n][0] - mnew_lo);
            p[n][1] = __expf(s[n][1] - mnew_lo);
            p[n][2] = __expf(s[n][2] - mnew_hi);
            p[n][3] = __expf(s[n][3] - mnew_hi);
            sum_lo += p[n][0] + p[n][1];
            sum_hi += p[n][2] + p[n][3];
        }
        sum_lo += __shfl_xor_sync(0xffffffffu, sum_lo, 1);
        sum_lo += __shfl_xor_sync(0xffffffffu, sum_lo, 2);
        sum_hi += __shfl_xor_sync(0xffffffffu, sum_hi, 1);
        sum_hi += __shfl_xor_sync(0xffffffffu, sum_hi, 2);
        l_lo = l_lo * alpha_lo + sum_lo;
        l_hi = l_hi * alpha_hi + sum_hi;

        // P a-fragments directly from registers (no smem round-trip)
        uint32_t Pa[4][4];
        #pragma unroll
        for (int kb = 0; kb < 4; kb++) {
            Pa[kb][0] = h2u(p[2 * kb][0],     p[2 * kb][1]);
            Pa[kb][1] = h2u(p[2 * kb][2],     p[2 * kb][3]);
            Pa[kb][2] = h2u(p[2 * kb + 1][0], p[2 * kb + 1][1]);
            Pa[kb][3] = h2u(p[2 * kb + 1][2], p[2 * kb + 1][3]);
        }

        #pragma unroll
        for (int n = 0; n < 8; n++) {
            O[n][0] *= alpha_lo; O[n][1] *= alpha_lo;
            O[n][2] *= alpha_hi; O[n][3] *= alpha_hi;
        }

        // O += P @ V   (B = V^T in smem: rows=hd, cols=key)
        #pragma unroll
        for (int kb = 0; kb < 4; kb++) {
            #pragma unroll
            for (int n = 0; n < 8; n++) {
                const __half* vb = Vs + (n * 8 + g) * FP + kb * 16 + 2 * tg;
                uint32_t b0 = *reinterpret_cast<const uint32_t*>(vb);
                uint32_t b1 = *reinterpret_cast<const uint32_t*>(vb + 8);
                mma_f16(O[n], Pa[kb], b0, b1);
            }
        }
    }

    // epilogue: normalize, write half to g_ctx
    float inv_lo = 1.f / l_lo, inv_hi = 1.f / l_hi;
    size_t row_lo = ((size_t)batch * SEQ + qrow_lo) * DIM + head * HD;
    size_t row_hi = row_lo + (size_t)8 * DIM;
    #pragma unroll
    for (int n = 0; n < 8; n++) {
        int col = n * 8 + 2 * tg;
        *reinterpret_cast<uint32_t*>(&g_ctx[row_lo + col]) =
            h2u(O[n][0] * inv_lo, O[n][1] * inv_lo);
        *reinterpret_cast<uint32_t*>(&g_ctx[row_hi + col]) =
            h2u(O[n][2] * inv_hi, O[n][3] * inv_hi);
    }
}

// ---------------- launch ----------------------------------------------------
extern "C" void kernel_launch(void* const* d_in, const int* in_sizes, int n_in,
                              void* d_out, int out_size)
{
    const float* x         = (const float*)d_in[0];
    const float* w_q       = (const float*)d_in[1];
    const float* w_k       = (const float*)d_in[2];
    const float* w_v       = (const float*)d_in[3];
    const float* in_proj_w = (const float*)d_in[4];
    const float* in_proj_b = (const float*)d_in[5];
    const float* out_w     = (const float*)d_in[6];
    const float* out_b     = (const float*)d_in[7];
    float* out = (float*)d_out;

    void *p_x, *p_wq, *p_wk, *p_wv, *p_wip, *p_wo;
    cudaGetSymbolAddress(&p_x,   g_x);
    cudaGetSymbolAddress(&p_wq,  g_wq);
    cudaGetSymbolAddress(&p_wk,  g_wk);
    cudaGetSymbolAddress(&p_wv,  g_wv);
    cudaGetSymbolAddress(&p_wip, g_wip);
    cudaGetSymbolAddress(&p_wo,  g_wo);

    setup_theta_kernel<<<1, 256>>>();
    setup_cs_kernel<<<SEQ, 256>>>();

    F2HJobs jobs;
    jobs.src[0] = (const float4*)x;         jobs.dst[0] = (__half2*)p_x;   jobs.n4[0] = BM * DIM / 4;
    jobs.src[1] = (const float4*)in_proj_w; jobs.dst[1] = (__half2*)p_wip; jobs.n4[1] = 3 * DIM * DIM / 4;
    jobs.src[2] = (const float4*)w_q;       jobs.dst[2] = (__half2*)p_wq;  jobs.n4[2] = DIM * DIM / 4;
    jobs.src[3] = (const float4*)w_k;       jobs.dst[3] = (__half2*)p_wk;  jobs.n4[3] = DIM * DIM / 4;
    jobs.src[4] = (const float4*)w_v;       jobs.dst[4] = (__half2*)p_wv;  jobs.n4[4] = DIM * DIM / 4;
    jobs.src[5] = (const float4*)out_w;     jobs.dst[5] = (__half2*)p_wo;  jobs.n4[5] = DIM * DIM / 4;
    f2h_all_kernel<<<1184, 256>>>(jobs);   // 8 CTAs/SM x 148

    cudaFuncSetAttribute(gemm128h<0>, cudaFuncAttributeMaxDynamicSharedMemorySize, GEMM_SMEM);
    cudaFuncSetAttribute(gemm128h<1>, cudaFuncAttributeMaxDynamicSharedMemorySize, GEMM_SMEM);
    cudaFuncSetAttribute(gemm128h<2>, cudaFuncAttributeMaxDynamicSharedMemorySize, GEMM_SMEM);
    cudaFuncSetAttribute(flash3_kernel, cudaFuncAttributeMaxDynamicSharedMemorySize, FLASH_SMEM);

    // rot(x @ W^T) for q,k,v  (N = 1536)
    gemm128h<0><<<dim3(12, 128), 128, GEMM_SMEM>>>(nullptr, nullptr);
    // in_proj + bias -> QKV (scatter, Q scaled, V transposed)
    gemm128h<1><<<dim3(12, 128), 128, GEMM_SMEM>>>(in_proj_b, nullptr);
    // causal flash attention -> g_ctx   (6th launch: ncu -s 5 captures this)
    flash3_kernel<<<dim3(64, 16), 256, FLASH_SMEM>>>();
    // out projection + bias -> d_out (fp32)
    gemm128h<2><<<dim3(4, 128), 128, GEMM_SMEM>>>(out_b, out);
}